// round 1
// baseline (speedup 1.0000x reference)
#include <cuda_runtime.h>
#include <math.h>
#include <stdint.h>

// Problem constants
#define BQ 8
#define TQ 4096
#define NTOK (BQ*TQ)          // 32768 tokens
#define EMB 512
#define HEADS 8
#define ES 64
#define MF 32                 // random features
#define HID (4*EMB)           // 2048
#define LN_EPS 1e-5f

// -------- scratch (device globals; no runtime allocation) --------
__device__ float g_h2[NTOK*EMB];              // LN output (reused for LN1 and LN2)
__device__ float g_v[(size_t)NTOK*HEADS*ES];  // v  [tok][h][64]
__device__ float g_qp[(size_t)NTOK*HEADS*MF]; // qp [tok][h][32]
__device__ float g_kp[(size_t)NTOK*HEADS*MF]; // kp [tok][h][32]
__device__ float g_kptv_part[16*64*ES*MF];    // partials [chunk][bh][e][m]
__device__ float g_ksum_part[16*64*MF];
__device__ float g_kptv[64*ES*MF];            // [bh][e][m]
__device__ float g_ksum[64*MF];               // [bh][m]
__device__ float g_y[(size_t)NTOK*EMB];
__device__ float g_x1[(size_t)NTOK*EMB];
__device__ float g_hid[(size_t)NTOK*HID];     // 268MB

// ---------------- LayerNorm: warp per token ----------------
__global__ void ln_kernel(const float* __restrict__ x, const float* __restrict__ g,
                          const float* __restrict__ b, float* __restrict__ out) {
    int tok  = blockIdx.x * 8 + (threadIdx.x >> 5);
    int lane = threadIdx.x & 31;
    const float4* xr = (const float4*)(x + (size_t)tok * EMB);
    float4 v[4];
    float s = 0.f, sq = 0.f;
    #pragma unroll
    for (int i = 0; i < 4; i++) {
        v[i] = xr[lane + 32*i];
        s  += v[i].x + v[i].y + v[i].z + v[i].w;
        sq += v[i].x*v[i].x + v[i].y*v[i].y + v[i].z*v[i].z + v[i].w*v[i].w;
    }
    #pragma unroll
    for (int o = 16; o; o >>= 1) {
        s  += __shfl_xor_sync(0xffffffffu, s,  o);
        sq += __shfl_xor_sync(0xffffffffu, sq, o);
    }
    float mean = s * (1.0f/EMB);
    float var  = sq * (1.0f/EMB) - mean*mean;
    float rstd = rsqrtf(var + LN_EPS);
    const float4* g4 = (const float4*)g;
    const float4* b4 = (const float4*)b;
    float4* orow = (float4*)(out + (size_t)tok * EMB);
    #pragma unroll
    for (int i = 0; i < 4; i++) {
        float4 gg = g4[lane + 32*i], bb = b4[lane + 32*i];
        float4 o;
        o.x = (v[i].x - mean) * rstd * gg.x + bb.x;
        o.y = (v[i].y - mean) * rstd * gg.y + bb.y;
        o.z = (v[i].z - mean) * rstd * gg.z + bb.z;
        o.w = (v[i].w - mean) * rstd * gg.w + bb.w;
        orow[lane + 32*i] = o;
    }
}

// ---------------- kqv + prm_exp (8 tokens per block) ----------------
// dyn smem floats: sh_h 4096 | wk_t 12288 | wr_t 2048 | sbias 192 | skqv 1536 | sxd 16
#define K1_SMEM_FLOATS (4096 + 12288 + 2048 + 192 + 1536 + 16)
__global__ void kqv_prm_kernel(const float* __restrict__ hN, const float* __restrict__ kqv_w,
                               const float* __restrict__ kqv_b, const float* __restrict__ wrf,
                               float* __restrict__ gv, float* __restrict__ gkp,
                               float* __restrict__ gqp) {
    extern __shared__ float sm[];
    float* sh_h  = sm;                  // [8][512]
    float* wk_t  = sm + 4096;           // [64][192] (e-major)
    float* wr_t  = wk_t + 12288;        // [64][32]
    float* sbias = wr_t + 2048;         // [192]
    float* skqv  = sbias + 192;         // [8][192]
    float* sxd   = skqv + 1536;         // [16] = [tok][which]
    int tid = threadIdx.x;
    size_t t0 = (size_t)blockIdx.x * 8;

    { // load 8 normalized token rows
        const float4* src = (const float4*)(hN + t0 * EMB);
        float4* dst = (float4*)sh_h;
        #pragma unroll
        for (int i = 0; i < 4; i++) dst[tid + 256*i] = src[tid + 256*i];
    }
    // load kqv_w transposed: wk_t[e][f]
    #pragma unroll
    for (int i = 0; i < 12; i++) {
        int j = tid + 256*i;           // float4 index, 3072 total
        int f = j >> 4, e0 = (j & 15) << 2;
        float4 w4 = ((const float4*)kqv_w)[j];
        wk_t[(e0+0)*192 + f] = w4.x;
        wk_t[(e0+1)*192 + f] = w4.y;
        wk_t[(e0+2)*192 + f] = w4.z;
        wk_t[(e0+3)*192 + f] = w4.w;
    }
    // load w transposed: wr_t[e][m]
    #pragma unroll
    for (int i = 0; i < 2; i++) {
        int j = tid + 256*i;           // 512 float4 total
        int m = j >> 4, e0 = (j & 15) << 2;
        float4 w4 = ((const float4*)wrf)[j];
        wr_t[(e0+0)*32 + m] = w4.x;
        wr_t[(e0+1)*32 + m] = w4.y;
        wr_t[(e0+2)*32 + m] = w4.z;
        wr_t[(e0+3)*32 + m] = w4.w;
    }
    if (tid < 192) sbias[tid] = kqv_b[tid];
    __syncthreads();

    int fg = tid & 63, tg = tid >> 6;
    int f0 = fg * 3, tokA = tg * 2;

    for (int hd = 0; hd < HEADS; hd++) {
        // ---- kqv tile: each thread 3 f x 2 tok ----
        float a00=0,a01=0,a10=0,a11=0,a20=0,a21=0;
        const float* hb = sh_h + hd * 64;
        #pragma unroll 8
        for (int e = 0; e < 64; e++) {
            float w0 = wk_t[e*192 + f0];
            float w1 = wk_t[e*192 + f0 + 1];
            float w2 = wk_t[e*192 + f0 + 2];
            float h0 = hb[tokA*512 + e];
            float h1 = hb[(tokA+1)*512 + e];
            a00 += w0*h0; a01 += w0*h1;
            a10 += w1*h0; a11 += w1*h1;
            a20 += w2*h0; a21 += w2*h1;
        }
        skqv[tokA*192 + f0 + 0] = a00 + sbias[f0+0];
        skqv[tokA*192 + f0 + 1] = a10 + sbias[f0+1];
        skqv[tokA*192 + f0 + 2] = a20 + sbias[f0+2];
        skqv[(tokA+1)*192 + f0 + 0] = a01 + sbias[f0+0];
        skqv[(tokA+1)*192 + f0 + 1] = a11 + sbias[f0+1];
        skqv[(tokA+1)*192 + f0 + 2] = a21 + sbias[f0+2];
        __syncthreads();

        // ---- write v ----
        #pragma unroll
        for (int i = 0; i < 2; i++) {
            int idx = tid + 256*i;     // 512 values: 8 tok x 64 e
            int tok = idx >> 6, e = idx & 63;
            gv[(((t0 + tok) * HEADS) + hd) * ES + e] = skqv[tok*192 + 128 + e];
        }
        // ---- xd per (tok, k/q) ----
        if (tid < 16) {
            int tok = tid >> 1, which = tid & 1;
            const float* z = skqv + tok*192 + which*64;
            float s = 0.f;
            #pragma unroll 8
            for (int e = 0; e < 64; e++) { float zz = z[e]; s += zz*zz; }
            sxd[tid] = 0.5f * s;
        }
        __syncthreads();

        // ---- wtx + exp ----
        #pragma unroll
        for (int i = 0; i < 2; i++) {
            int idx = tid + 256*i;     // 512 = 8 tok x 2 which x 32 m
            int m = idx & 31, which = (idx >> 5) & 1, tok = idx >> 6;
            const float* z = skqv + tok*192 + which*64;
            float a = 0.f;
            #pragma unroll 8
            for (int e = 0; e < 64; e++) a += z[e] * wr_t[e*32 + m];
            float val = expf(a - sxd[tok*2 + which]) * 0.17677669529663689f; // 1/sqrt(32)
            float* dst = which ? gqp : gkp;
            dst[(((t0 + tok) * HEADS) + hd) * MF + m] = val;
        }
        __syncthreads();  // before skqv reuse
    }
}

// ---------------- kptv / ksum partial reduction over T ----------------
__global__ void kpt_kernel(const float* __restrict__ gv, const float* __restrict__ gkp,
                           float* __restrict__ part_kptv, float* __restrict__ part_ksum) {
    int chunk = blockIdx.x;            // 0..15 (256 timesteps each)
    int bh = blockIdx.y;               // 0..63
    int b = bh >> 3, h = bh & 7;
    __shared__ float sv[16][64];
    __shared__ float skp[16][32];
    int tid = threadIdx.x, lane = tid & 31, wid = tid >> 5;
    float acc[8] = {0,0,0,0,0,0,0,0};
    float ks = 0.f;
    int t0 = chunk * 256;
    for (int st = 0; st < 16; st++) {
        int s0 = t0 + st * 16;
        __syncthreads();
        #pragma unroll
        for (int i = 0; i < 4; i++) {
            int idx = tid + 256*i;     // 1024 v floats
            int s = idx >> 6, e = idx & 63;
            sv[s][e] = gv[((((size_t)b*TQ + s0 + s) * HEADS) + h) * ES + e];
        }
        #pragma unroll
        for (int i = 0; i < 2; i++) {
            int idx = tid + 256*i;     // 512 kp floats
            int s = idx >> 5, m = idx & 31;
            skp[s][m] = gkp[((((size_t)b*TQ + s0 + s) * HEADS) + h) * MF + m];
        }
        __syncthreads();
        #pragma unroll
        for (int s = 0; s < 16; s++) {
            float kv = skp[s][lane];
            float4 va = *(const float4*)&sv[s][wid*8];
            float4 vb = *(const float4*)&sv[s][wid*8 + 4];
            acc[0] += va.x*kv; acc[1] += va.y*kv; acc[2] += va.z*kv; acc[3] += va.w*kv;
            acc[4] += vb.x*kv; acc[5] += vb.y*kv; acc[6] += vb.z*kv; acc[7] += vb.w*kv;
            if (wid == 0) ks += kv;
        }
    }
    size_t base = ((size_t)(chunk*64 + bh)) * (ES*MF);
    #pragma unroll
    for (int j = 0; j < 8; j++)
        part_kptv[base + (wid*8 + j)*MF + lane] = acc[j];
    if (wid == 0) part_ksum[(chunk*64 + bh)*MF + lane] = ks;
}

__global__ void reduce_kernel(const float* __restrict__ pk, const float* __restrict__ ps,
                              float* __restrict__ kptv, float* __restrict__ ksum) {
    int bid = blockIdx.x;
    if (bid < 512) {
        int idx = bid * 256 + threadIdx.x;   // 0..131071
        int bh = idx >> 11, em = idx & 2047;
        float s = 0.f;
        #pragma unroll
        for (int c = 0; c < 16; c++) s += pk[((size_t)(c*64 + bh)) * 2048 + em];
        kptv[idx] = s;
    } else {
        #pragma unroll
        for (int j = 0; j < 8; j++) {
            int idx = threadIdx.x * 8 + j;   // 0..2047
            int bh = idx >> 5, m = idx & 31;
            float s = 0.f;
            #pragma unroll
            for (int c = 0; c < 16; c++) s += ps[(c*64 + bh)*MF + m];
            ksum[idx] = s;
        }
    }
}

// ---------------- y = (qp . kptv) / D ----------------
__global__ void y_kernel(const float* __restrict__ gqp, const float* __restrict__ kptv,
                         const float* __restrict__ ksum, float* __restrict__ gy) {
    int bh = blockIdx.y, b = bh >> 3, h = bh & 7;
    __shared__ float sk[64*33];   // padded [e][m]
    __shared__ float sks[32];
    int tid = threadIdx.x, lane = tid & 31, wid = tid >> 5;
    #pragma unroll
    for (int i = 0; i < 8; i++) {
        int idx = tid + 256*i;    // 2048
        sk[(idx >> 5)*33 + (idx & 31)] = kptv[(size_t)bh*2048 + idx];
    }
    if (tid < 32) sks[tid] = ksum[bh*32 + tid];
    __syncthreads();
    float ksv = sks[lane];
    for (int it = 0; it < 32; it++) {
        int t = blockIdx.x * 256 + wid * 32 + it;
        float qpv = gqp[((((size_t)b*TQ + t) * HEADS) + h) * MF + lane];
        float d = qpv * ksv;
        #pragma unroll
        for (int o = 16; o; o >>= 1) d += __shfl_xor_sync(0xffffffffu, d, o);
        float a0 = 0.f, a1 = 0.f;
        #pragma unroll
        for (int m = 0; m < 32; m++) {
            float qm = __shfl_sync(0xffffffffu, qpv, m);
            a0 += qm * sk[lane*33 + m];
            a1 += qm * sk[(lane+32)*33 + m];
        }
        float inv = 1.0f / d;
        float* dst = gy + ((size_t)b*TQ + t) * EMB + h * ES;
        dst[lane]      = a0 * inv;
        dst[lane + 32] = a1 * inv;
    }
}

// ---------------- 128x128x8 SGEMM, C = A(MxK) * Bw(NxK)^T + epilogue ----------------
// GELU=0: out = acc + bias[n] + res[row*N+n]
// GELU=1: out = gelu_exact(acc + bias[n])
template<int GELU>
__global__ void __launch_bounds__(256) sgemm_kernel(const float* __restrict__ A,
        const float* __restrict__ Bw, const float* __restrict__ bias,
        const float* __restrict__ res, float* __restrict__ C,
        int M, int N, int K) {
    __shared__ float As[8][128];
    __shared__ float Bs[8][128];
    int tid = threadIdx.x;
    int rowBase = blockIdx.y * 128, colBase = blockIdx.x * 128;
    int tx = tid & 15, ty = tid >> 4;
    int lr = tid >> 1, lc = (tid & 1) << 2;
    const float* Ap = A  + (size_t)(rowBase + lr) * K + lc;
    const float* Bp = Bw + (size_t)(colBase + lr) * K + lc;
    float acc[8][8];
    #pragma unroll
    for (int i = 0; i < 8; i++)
        #pragma unroll
        for (int j = 0; j < 8; j++) acc[i][j] = 0.f;

    float4 an = *(const float4*)Ap;
    float4 bn = *(const float4*)Bp;
    int nk = K >> 3;
    for (int kt = 0; kt < nk; kt++) {
        As[lc+0][lr] = an.x; As[lc+1][lr] = an.y; As[lc+2][lr] = an.z; As[lc+3][lr] = an.w;
        Bs[lc+0][lr] = bn.x; Bs[lc+1][lr] = bn.y; Bs[lc+2][lr] = bn.z; Bs[lc+3][lr] = bn.w;
        __syncthreads();
        if (kt + 1 < nk) {
            an = *(const float4*)(Ap + (size_t)(kt+1)*8);
            bn = *(const float4*)(Bp + (size_t)(kt+1)*8);
        }
        #pragma unroll
        for (int k = 0; k < 8; k++) {
            float4 a0 = *(const float4*)&As[k][ty*8];
            float4 a1 = *(const float4*)&As[k][ty*8 + 4];
            float4 b0 = *(const float4*)&Bs[k][tx*8];
            float4 b1 = *(const float4*)&Bs[k][tx*8 + 4];
            float ar[8] = {a0.x,a0.y,a0.z,a0.w,a1.x,a1.y,a1.z,a1.w};
            float br[8] = {b0.x,b0.y,b0.z,b0.w,b1.x,b1.y,b1.z,b1.w};
            #pragma unroll
            for (int i = 0; i < 8; i++)
                #pragma unroll
                for (int j = 0; j < 8; j++)
                    acc[i][j] += ar[i] * br[j];
        }
        __syncthreads();
    }
    #pragma unroll
    for (int i = 0; i < 8; i++) {
        int row = rowBase + ty*8 + i;
        float* crow = C + (size_t)row * N + colBase + tx*8;
        const float* rrow = (GELU == 0) ? (res + (size_t)row * N + colBase + tx*8) : (const float*)0;
        #pragma unroll
        for (int j = 0; j < 8; j++) {
            float v = acc[i][j] + bias[colBase + tx*8 + j];
            if (GELU) v = 0.5f * v * (1.0f + erff(v * 0.70710678118654752f));
            else      v += rrow[j];
            crow[j] = v;
        }
    }
}

// ---------------- launch ----------------
extern "C" void kernel_launch(void* const* d_in, const int* in_sizes, int n_in,
                              void* d_out, int out_size) {
    const float* x      = (const float*)d_in[0];
    const float* wrf    = (const float*)d_in[1];
    const float* kqv_w  = (const float*)d_in[2];
    const float* kqv_b  = (const float*)d_in[3];
    const float* proj_w = (const float*)d_in[4];
    const float* proj_b = (const float*)d_in[5];
    const float* ln1_g  = (const float*)d_in[6];
    const float* ln1_b  = (const float*)d_in[7];
    const float* ln2_g  = (const float*)d_in[8];
    const float* ln2_b  = (const float*)d_in[9];
    const float* mlp_w1 = (const float*)d_in[10];
    const float* mlp_b1 = (const float*)d_in[11];
    const float* mlp_w2 = (const float*)d_in[12];
    const float* mlp_b2 = (const float*)d_in[13];
    float* out = (float*)d_out;

    float *p_h2, *p_v, *p_qp, *p_kp, *p_pk, *p_ps, *p_kptv, *p_ksum, *p_y, *p_x1, *p_hid;
    cudaGetSymbolAddress((void**)&p_h2,   g_h2);
    cudaGetSymbolAddress((void**)&p_v,    g_v);
    cudaGetSymbolAddress((void**)&p_qp,   g_qp);
    cudaGetSymbolAddress((void**)&p_kp,   g_kp);
    cudaGetSymbolAddress((void**)&p_pk,   g_kptv_part);
    cudaGetSymbolAddress((void**)&p_ps,   g_ksum_part);
    cudaGetSymbolAddress((void**)&p_kptv, g_kptv);
    cudaGetSymbolAddress((void**)&p_ksum, g_ksum);
    cudaGetSymbolAddress((void**)&p_y,    g_y);
    cudaGetSymbolAddress((void**)&p_x1,   g_x1);
    cudaGetSymbolAddress((void**)&p_hid,  g_hid);

    const size_t k1_smem = (size_t)K1_SMEM_FLOATS * sizeof(float);  // ~80.7KB
    cudaFuncSetAttribute(kqv_prm_kernel, cudaFuncAttributeMaxDynamicSharedMemorySize,
                         (int)k1_smem);

    // 1. LN1
    ln_kernel<<<NTOK/8, 256>>>(x, ln1_g, ln1_b, p_h2);
    // 2. kqv + prm_exp
    kqv_prm_kernel<<<NTOK/8, 256, k1_smem>>>(p_h2, kqv_w, kqv_b, wrf, p_v, p_kp, p_qp);
    // 3. kptv/ksum partials over T
    kpt_kernel<<<dim3(16, 64), 256>>>(p_v, p_kp, p_pk, p_ps);
    // 4. reduce partials
    reduce_kernel<<<513, 256>>>(p_pk, p_ps, p_kptv, p_ksum);
    // 5. y = qp.kptv / D
    y_kernel<<<dim3(TQ/256, 64), 256>>>(p_qp, p_kptv, p_ksum, p_y);
    // 6. attn proj + residual -> x1
    sgemm_kernel<0><<<dim3(EMB/128, NTOK/128), 256>>>(p_y, proj_w, proj_b, x, p_x1,
                                                      NTOK, EMB, EMB);
    // 7. LN2 -> h2 (buffer reuse)
    ln_kernel<<<NTOK/8, 256>>>(p_x1, ln2_g, ln2_b, p_h2);
    // 8. mlp1 + gelu -> hid
    sgemm_kernel<1><<<dim3(HID/128, NTOK/128), 256>>>(p_h2, mlp_w1, mlp_b1, (const float*)0,
                                                      p_hid, NTOK, HID, EMB);
    // 9. mlp2 + residual -> out
    sgemm_kernel<0><<<dim3(EMB/128, NTOK/128), 256>>>(p_hid, mlp_w2, mlp_b2, p_x1, out,
                                                      NTOK, EMB, HID);
}

// round 4
// speedup vs baseline: 1.7661x; 1.7661x over previous
#include <cuda_runtime.h>
#include <cuda_bf16.h>
#include <math.h>
#include <stdint.h>

// Problem constants
#define BQ 8
#define TQ 4096
#define NTOK (BQ*TQ)          // 32768 tokens
#define EMB 512
#define HEADS 8
#define ES 64
#define MF 32                 // random features
#define HID (4*EMB)           // 2048
#define LN_EPS 1e-5f

__device__ __forceinline__ uint32_t smem_to_u32(const void* smem_ptr) {
    uint32_t addr;
    asm("{ .reg .u64 tmp; cvta.to.shared.u64 tmp, %1; cvt.u32.u64 %0, tmp; }"
        : "=r"(addr) : "l"(smem_ptr));
    return addr;
}

__device__ __forceinline__ void cp_async16(uint32_t saddr, const void* gaddr) {
    asm volatile("cp.async.cg.shared.global [%0], [%1], 16;" :: "r"(saddr), "l"(gaddr));
}
#define CP_COMMIT() asm volatile("cp.async.commit_group;" ::: "memory")
#define CP_WAIT0()  asm volatile("cp.async.wait_group 0;" ::: "memory")
#define CP_WAIT1()  asm volatile("cp.async.wait_group 1;" ::: "memory")

__device__ __forceinline__ void ldsm_x4(uint32_t& r0, uint32_t& r1, uint32_t& r2, uint32_t& r3,
                                        uint32_t addr) {
    asm volatile("ldmatrix.sync.aligned.m8n8.x4.shared.b16 {%0,%1,%2,%3}, [%4];"
        : "=r"(r0), "=r"(r1), "=r"(r2), "=r"(r3) : "r"(addr));
}

__device__ __forceinline__ void mma_bf16(float* c, const uint32_t* a, const uint32_t* b) {
    asm volatile(
        "mma.sync.aligned.m16n8k16.row.col.f32.bf16.bf16.f32 "
        "{%0,%1,%2,%3}, {%4,%5,%6,%7}, {%8,%9}, {%0,%1,%2,%3};"
        : "+f"(c[0]), "+f"(c[1]), "+f"(c[2]), "+f"(c[3])
        : "r"(a[0]), "r"(a[1]), "r"(a[2]), "r"(a[3]), "r"(b[0]), "r"(b[1]));
}

__device__ __forceinline__ void split2(float x, __nv_bfloat16& h, __nv_bfloat16& l) {
    h = __float2bfloat16(x);
    l = __float2bfloat16(x - __bfloat162float(h));
}

// -------- scratch (device globals; no runtime allocation) --------
__device__ float g_h2[(size_t)NTOK*EMB];
__device__ float g_v[(size_t)NTOK*HEADS*ES];
__device__ float g_qp[(size_t)NTOK*HEADS*MF];
__device__ float g_kp[(size_t)NTOK*HEADS*MF];
__device__ float g_kptv_part[16*64*ES*MF];
__device__ float g_ksum_part[16*64*MF];
__device__ float g_kptv[64*ES*MF];
__device__ float g_ksum[64*MF];
__device__ float g_x1[(size_t)NTOK*EMB];
__device__ __align__(16) __nv_bfloat16 g_h2h[(size_t)NTOK*EMB], g_h2l[(size_t)NTOK*EMB];
__device__ __align__(16) __nv_bfloat16 g_yh[(size_t)NTOK*EMB],  g_yl[(size_t)NTOK*EMB];
__device__ __align__(16) __nv_bfloat16 g_hidh[(size_t)NTOK*HID], g_hidl[(size_t)NTOK*HID];
__device__ __align__(16) __nv_bfloat16 g_pwh[EMB*EMB],  g_pwl[EMB*EMB];
__device__ __align__(16) __nv_bfloat16 g_w1h[HID*EMB],  g_w1l[HID*EMB];
__device__ __align__(16) __nv_bfloat16 g_w2h[EMB*HID],  g_w2l[EMB*HID];

// ---------------- weight split conversion ----------------
__global__ void cvt_split_kernel(const float* __restrict__ w, __nv_bfloat16* __restrict__ hi,
                                 __nv_bfloat16* __restrict__ lo, int n4) {
    int i = blockIdx.x * 256 + threadIdx.x;
    if (i < n4) {
        float4 v = ((const float4*)w)[i];
        __nv_bfloat16 h[4], l[4];
        split2(v.x, h[0], l[0]); split2(v.y, h[1], l[1]);
        split2(v.z, h[2], l[2]); split2(v.w, h[3], l[3]);
        *(uint2*)(hi + (size_t)i*4) = *(uint2*)h;
        *(uint2*)(lo + (size_t)i*4) = *(uint2*)l;
    }
}

// ---------------- LayerNorm: warp per token ----------------
template<int MODE>
__global__ void ln_kernel(const float* __restrict__ x, const float* __restrict__ g,
                          const float* __restrict__ b, float* __restrict__ out,
                          __nv_bfloat16* __restrict__ ohi, __nv_bfloat16* __restrict__ olo) {
    int tok  = blockIdx.x * 8 + (threadIdx.x >> 5);
    int lane = threadIdx.x & 31;
    const float4* xr = (const float4*)(x + (size_t)tok * EMB);
    float4 v[4];
    float s = 0.f, sq = 0.f;
    #pragma unroll
    for (int i = 0; i < 4; i++) {
        v[i] = xr[lane + 32*i];
        s  += v[i].x + v[i].y + v[i].z + v[i].w;
        sq += v[i].x*v[i].x + v[i].y*v[i].y + v[i].z*v[i].z + v[i].w*v[i].w;
    }
    #pragma unroll
    for (int o = 16; o; o >>= 1) {
        s  += __shfl_xor_sync(0xffffffffu, s,  o);
        sq += __shfl_xor_sync(0xffffffffu, sq, o);
    }
    float mean = s * (1.0f/EMB);
    float var  = sq * (1.0f/EMB) - mean*mean;
    float rstd = rsqrtf(var + LN_EPS);
    const float4* g4 = (const float4*)g;
    const float4* b4 = (const float4*)b;
    #pragma unroll
    for (int i = 0; i < 4; i++) {
        float4 gg = g4[lane + 32*i], bb = b4[lane + 32*i];
        float4 o;
        o.x = (v[i].x - mean) * rstd * gg.x + bb.x;
        o.y = (v[i].y - mean) * rstd * gg.y + bb.y;
        o.z = (v[i].z - mean) * rstd * gg.z + bb.z;
        o.w = (v[i].w - mean) * rstd * gg.w + bb.w;
        if (MODE == 0) {
            ((float4*)(out + (size_t)tok * EMB))[lane + 32*i] = o;
        } else {
            size_t idx = (size_t)tok * EMB + (size_t)(lane + 32*i) * 4;
            __nv_bfloat16 h[4], l[4];
            split2(o.x, h[0], l[0]); split2(o.y, h[1], l[1]);
            split2(o.z, h[2], l[2]); split2(o.w, h[3], l[3]);
            *(uint2*)(ohi + idx) = *(uint2*)h;
            *(uint2*)(olo + idx) = *(uint2*)l;
        }
    }
}

// ---------------- kqv + prm_exp (8 tokens per block) ----------------
#define K1_SMEM_FLOATS (4096 + 12288 + 2048 + 192 + 1536 + 16)
__global__ void kqv_prm_kernel(const float* __restrict__ hN, const float* __restrict__ kqv_w,
                               const float* __restrict__ kqv_b, const float* __restrict__ wrf,
                               float* __restrict__ gv, float* __restrict__ gkp,
                               float* __restrict__ gqp) {
    extern __shared__ float sm[];
    float* sh_h  = sm;
    float* wk_t  = sm + 4096;
    float* wr_t  = wk_t + 12288;
    float* sbias = wr_t + 2048;
    float* skqv  = sbias + 192;
    float* sxd   = skqv + 1536;
    int tid = threadIdx.x;
    size_t t0 = (size_t)blockIdx.x * 8;

    {
        const float4* src = (const float4*)(hN + t0 * EMB);
        float4* dst = (float4*)sh_h;
        #pragma unroll
        for (int i = 0; i < 4; i++) dst[tid + 256*i] = src[tid + 256*i];
    }
    #pragma unroll
    for (int i = 0; i < 12; i++) {
        int j = tid + 256*i;
        int f = j >> 4, e0 = (j & 15) << 2;
        float4 w4 = ((const float4*)kqv_w)[j];
        wk_t[(e0+0)*192 + f] = w4.x;
        wk_t[(e0+1)*192 + f] = w4.y;
        wk_t[(e0+2)*192 + f] = w4.z;
        wk_t[(e0+3)*192 + f] = w4.w;
    }
    #pragma unroll
    for (int i = 0; i < 2; i++) {
        int j = tid + 256*i;
        int m = j >> 4, e0 = (j & 15) << 2;
        float4 w4 = ((const float4*)wrf)[j];
        wr_t[(e0+0)*32 + m] = w4.x;
        wr_t[(e0+1)*32 + m] = w4.y;
        wr_t[(e0+2)*32 + m] = w4.z;
        wr_t[(e0+3)*32 + m] = w4.w;
    }
    if (tid < 192) sbias[tid] = kqv_b[tid];
    __syncthreads();

    int fg = tid & 63, tg = tid >> 6;
    int f0 = fg * 3, tokA = tg * 2;

    for (int hd = 0; hd < HEADS; hd++) {
        float a00=0,a01=0,a10=0,a11=0,a20=0,a21=0;
        const float* hb = sh_h + hd * 64;
        #pragma unroll 8
        for (int e = 0; e < 64; e++) {
            float w0 = wk_t[e*192 + f0];
            float w1 = wk_t[e*192 + f0 + 1];
            float w2 = wk_t[e*192 + f0 + 2];
            float h0 = hb[tokA*512 + e];
            float h1 = hb[(tokA+1)*512 + e];
            a00 += w0*h0; a01 += w0*h1;
            a10 += w1*h0; a11 += w1*h1;
            a20 += w2*h0; a21 += w2*h1;
        }
        skqv[tokA*192 + f0 + 0] = a00 + sbias[f0+0];
        skqv[tokA*192 + f0 + 1] = a10 + sbias[f0+1];
        skqv[tokA*192 + f0 + 2] = a20 + sbias[f0+2];
        skqv[(tokA+1)*192 + f0 + 0] = a01 + sbias[f0+0];
        skqv[(tokA+1)*192 + f0 + 1] = a11 + sbias[f0+1];
        skqv[(tokA+1)*192 + f0 + 2] = a21 + sbias[f0+2];
        __syncthreads();

        #pragma unroll
        for (int i = 0; i < 2; i++) {
            int idx = tid + 256*i;
            int tok = idx >> 6, e = idx & 63;
            gv[(((t0 + tok) * HEADS) + hd) * ES + e] = skqv[tok*192 + 128 + e];
        }
        if (tid < 16) {
            int tok = tid >> 1, which = tid & 1;
            const float* z = skqv + tok*192 + which*64;
            float s = 0.f;
            #pragma unroll 8
            for (int e = 0; e < 64; e++) { float zz = z[e]; s += zz*zz; }
            sxd[tid] = 0.5f * s;
        }
        __syncthreads();

        #pragma unroll
        for (int i = 0; i < 2; i++) {
            int idx = tid + 256*i;
            int m = idx & 31, which = (idx >> 5) & 1, tok = idx >> 6;
            const float* z = skqv + tok*192 + which*64;
            float a = 0.f;
            #pragma unroll 8
            for (int e = 0; e < 64; e++) a += z[e] * wr_t[e*32 + m];
            float val = expf(a - sxd[tok*2 + which]) * 0.17677669529663689f;
            float* dst = which ? gqp : gkp;
            dst[(((t0 + tok) * HEADS) + hd) * MF + m] = val;
        }
        __syncthreads();
    }
}

// ---------------- kptv / ksum partial reduction over T ----------------
__global__ void kpt_kernel(const float* __restrict__ gv, const float* __restrict__ gkp,
                           float* __restrict__ part_kptv, float* __restrict__ part_ksum) {
    int chunk = blockIdx.x;
    int bh = blockIdx.y;
    int b = bh >> 3, h = bh & 7;
    __shared__ float sv[16][64];
    __shared__ float skp[16][32];
    int tid = threadIdx.x, lane = tid & 31, wid = tid >> 5;
    float acc[8] = {0,0,0,0,0,0,0,0};
    float ks = 0.f;
    int t0 = chunk * 256;
    for (int st = 0; st < 16; st++) {
        int s0 = t0 + st * 16;
        __syncthreads();
        #pragma unroll
        for (int i = 0; i < 4; i++) {
            int idx = tid + 256*i;
            int s = idx >> 6, e = idx & 63;
            sv[s][e] = gv[((((size_t)b*TQ + s0 + s) * HEADS) + h) * ES + e];
        }
        #pragma unroll
        for (int i = 0; i < 2; i++) {
            int idx = tid + 256*i;
            int s = idx >> 5, m = idx & 31;
            skp[s][m] = gkp[((((size_t)b*TQ + s0 + s) * HEADS) + h) * MF + m];
        }
        __syncthreads();
        #pragma unroll
        for (int s = 0; s < 16; s++) {
            float kv = skp[s][lane];
            float4 va = *(const float4*)&sv[s][wid*8];
            float4 vb = *(const float4*)&sv[s][wid*8 + 4];
            acc[0] += va.x*kv; acc[1] += va.y*kv; acc[2] += va.z*kv; acc[3] += va.w*kv;
            acc[4] += vb.x*kv; acc[5] += vb.y*kv; acc[6] += vb.z*kv; acc[7] += vb.w*kv;
            if (wid == 0) ks += kv;
        }
    }
    size_t base = ((size_t)(chunk*64 + bh)) * (ES*MF);
    #pragma unroll
    for (int j = 0; j < 8; j++)
        part_kptv[base + (wid*8 + j)*MF + lane] = acc[j];
    if (wid == 0) part_ksum[(chunk*64 + bh)*MF + lane] = ks;
}

__global__ void reduce_kernel(const float* __restrict__ pk, const float* __restrict__ ps,
                              float* __restrict__ kptv, float* __restrict__ ksum) {
    int bid = blockIdx.x;
    if (bid < 512) {
        int idx = bid * 256 + threadIdx.x;
        int bh = idx >> 11;
        float s = 0.f;
        #pragma unroll
        for (int c = 0; c < 16; c++) s += pk[((size_t)(c*64 + bh)) * 2048 + (idx & 2047)];
        kptv[idx] = s;
    } else {
        #pragma unroll
        for (int j = 0; j < 8; j++) {
            int idx = threadIdx.x * 8 + j;
            int bh = idx >> 5, m = idx & 31;
            float s = 0.f;
            #pragma unroll
            for (int c = 0; c < 16; c++) s += ps[(c*64 + bh)*MF + m];
            ksum[idx] = s;
        }
    }
}

// ---------------- y = (qp . kptv) / D  -> bf16 hi/lo planes ----------------
__global__ void y_kernel(const float* __restrict__ gqp, const float* __restrict__ kptv,
                         const float* __restrict__ ksum, __nv_bfloat16* __restrict__ yh,
                         __nv_bfloat16* __restrict__ yl) {
    int bh = blockIdx.y, b = bh >> 3, h = bh & 7;
    __shared__ float sk[64*33];
    __shared__ float sks[32];
    int tid = threadIdx.x, lane = tid & 31, wid = tid >> 5;
    #pragma unroll
    for (int i = 0; i < 8; i++) {
        int idx = tid + 256*i;
        sk[(idx >> 5)*33 + (idx & 31)] = kptv[(size_t)bh*2048 + idx];
    }
    if (tid < 32) sks[tid] = ksum[bh*32 + tid];
    __syncthreads();
    float ksv = sks[lane];
    for (int it = 0; it < 32; it++) {
        int t = blockIdx.x * 256 + wid * 32 + it;
        float qpv = gqp[((((size_t)b*TQ + t) * HEADS) + h) * MF + lane];
        float d = qpv * ksv;
        #pragma unroll
        for (int o = 16; o; o >>= 1) d += __shfl_xor_sync(0xffffffffu, d, o);
        float a0 = 0.f, a1 = 0.f;
        #pragma unroll
        for (int m = 0; m < 32; m++) {
            float qm = __shfl_sync(0xffffffffu, qpv, m);
            a0 += qm * sk[lane*33 + m];
            a1 += qm * sk[(lane+32)*33 + m];
        }
        float inv = 1.0f / d;
        size_t off = ((size_t)b*TQ + t) * EMB + h * ES;
        float v0 = a0 * inv, v1 = a1 * inv;
        __nv_bfloat16 h0, l0, h1, l1;
        split2(v0, h0, l0);
        split2(v1, h1, l1);
        yh[off + lane]      = h0;  yl[off + lane]      = l0;
        yh[off + lane + 32] = h1;  yl[off + lane + 32] = l1;
    }
}

// ============== mma.sync bf16-split GEMM: C = A(MxK) * W(NxK)^T + epilogue ==============
// 128x128 CTA tile, 8 warps (4m x 2n), warp tile 32x64, chunk K=32, cp.async double buffer.
// ROW_STRIDE=80: 16B-aligned rows AND 80*row mod 128 hits 8 distinct 16B banks per 8 rows.
#define ROW_STRIDE 80
#define PLANE_BYTES (128*ROW_STRIDE)      // 10240
#define BUF_BYTES (4*PLANE_BYTES)         // 40960
#define GEMM_SMEM (2*BUF_BYTES)           // 81920

template<int EPI>
__global__ __launch_bounds__(256, 1)
void gemm_mma(const __nv_bfloat16* __restrict__ Ah, const __nv_bfloat16* __restrict__ Al,
              const __nv_bfloat16* __restrict__ Bh, const __nv_bfloat16* __restrict__ Bl,
              const float* __restrict__ bias, const float* __restrict__ res,
              float* __restrict__ Cf, __nv_bfloat16* __restrict__ Chi,
              __nv_bfloat16* __restrict__ Clo, int N, int K) {
    extern __shared__ char gsm[];
    uint32_t sb = smem_to_u32(gsm);
    int tid = threadIdx.x, lane = tid & 31, wid = tid >> 5;
    int rowBase = blockIdx.y * 128, colBase = blockIdx.x * 128;

    int wm = wid & 3, wn = wid >> 2;      // 4x2 warp grid
    int m0 = wm * 32, n0 = wn * 64;

    float acc[2][8][4];
    #pragma unroll
    for (int i = 0; i < 2; i++)
        #pragma unroll
        for (int j = 0; j < 8; j++)
            #pragma unroll
            for (int q = 0; q < 4; q++) acc[i][j][q] = 0.f;

    // per-lane ldmatrix base offsets (within plane, k0=0)
    uint32_t a_off = (uint32_t)(m0 + (lane & 15)) * ROW_STRIDE + ((lane >> 4) * 8) * 2;
    uint32_t b_off = (uint32_t)(n0 + (lane & 7) + ((lane >> 4) << 3)) * ROW_STRIDE
                   + (((lane >> 3) & 1) * 8) * 2;

    // loader: 4 planes x 128 rows x 64B data, 2048 x 16B transfers, 8 per thread
    auto load_chunk = [&](int buf, int k0) {
        uint32_t sbase = sb + buf * BUF_BYTES;
        int idx = tid * 2;
        int row = idx >> 2, c = idx & 3;          // c in {0, 2}
        uint32_t so  = (uint32_t)row * ROW_STRIDE + c * 16;
        uint32_t so1 = so + 16;
        size_t goA = (size_t)(rowBase + row) * K + k0 + c * 8;
        size_t goB = (size_t)(colBase + row) * K + k0 + c * 8;
        cp_async16(sbase + so,                     Ah + goA);
        cp_async16(sbase + so1,                    Ah + goA + 8);
        cp_async16(sbase + PLANE_BYTES   + so,     Al + goA);
        cp_async16(sbase + PLANE_BYTES   + so1,    Al + goA + 8);
        cp_async16(sbase + 2*PLANE_BYTES + so,     Bh + goB);
        cp_async16(sbase + 2*PLANE_BYTES + so1,    Bh + goB + 8);
        cp_async16(sbase + 3*PLANE_BYTES + so,     Bl + goB);
        cp_async16(sbase + 3*PLANE_BYTES + so1,    Bl + goB + 8);
    };

    int NC = K >> 5;
    load_chunk(0, 0);
    CP_COMMIT();

    for (int c = 0; c < NC; c++) {
        int buf = c & 1;
        if (c + 1 < NC) {
            load_chunk(buf ^ 1, (c + 1) << 5);
            CP_COMMIT();
            CP_WAIT1();
        } else {
            CP_WAIT0();
        }
        __syncthreads();

        uint32_t pA = sb + buf * BUF_BYTES;
        #pragma unroll
        for (int ks = 0; ks < 2; ks++) {
            uint32_t kadd = ks * 32;     // 16 bf16 = 32 bytes
            uint32_t ah[2][4], al[2][4], bh[8][2], bl[8][2];
            #pragma unroll
            for (int mt = 0; mt < 2; mt++) {
                uint32_t ad = pA + a_off + (uint32_t)mt * (16 * ROW_STRIDE) + kadd;
                ldsm_x4(ah[mt][0], ah[mt][1], ah[mt][2], ah[mt][3], ad);
                ldsm_x4(al[mt][0], al[mt][1], al[mt][2], al[mt][3], ad + PLANE_BYTES);
            }
            #pragma unroll
            for (int ng = 0; ng < 4; ng++) {
                uint32_t bd = pA + 2*PLANE_BYTES + b_off + (uint32_t)ng * (16 * ROW_STRIDE) + kadd;
                ldsm_x4(bh[2*ng][0], bh[2*ng][1], bh[2*ng+1][0], bh[2*ng+1][1], bd);
                ldsm_x4(bl[2*ng][0], bl[2*ng][1], bl[2*ng+1][0], bl[2*ng+1][1], bd + PLANE_BYTES);
            }
            #pragma unroll
            for (int mt = 0; mt < 2; mt++)
                #pragma unroll
                for (int nt = 0; nt < 8; nt++) {
                    mma_bf16(acc[mt][nt], ah[mt], bh[nt]);
                    mma_bf16(acc[mt][nt], ah[mt], bl[nt]);
                    mma_bf16(acc[mt][nt], al[mt], bh[nt]);
                }
        }
        __syncthreads();
    }

    // ---- epilogue ----
    int rbase = rowBase + m0 + (lane >> 2);
    int cbase = colBase + n0 + (lane & 3) * 2;
    #pragma unroll
    for (int mt = 0; mt < 2; mt++) {
        #pragma unroll
        for (int half = 0; half < 2; half++) {
            int row = rbase + mt * 16 + half * 8;
            if (EPI == 0) {
                float* crow = Cf + (size_t)row * N;
                const float* rrow = res + (size_t)row * N;
                #pragma unroll
                for (int nt = 0; nt < 8; nt++) {
                    int col = cbase + nt * 8;
                    float2 o;
                    o.x = acc[mt][nt][half*2+0] + bias[col]   + rrow[col];
                    o.y = acc[mt][nt][half*2+1] + bias[col+1] + rrow[col+1];
                    *(float2*)(crow + col) = o;
                }
            } else {
                __nv_bfloat16* hrow = Chi + (size_t)row * N;
                __nv_bfloat16* lrow = Clo + (size_t)row * N;
                #pragma unroll
                for (int nt = 0; nt < 8; nt++) {
                    int col = cbase + nt * 8;
                    float v0 = acc[mt][nt][half*2+0] + bias[col];
                    float v1 = acc[mt][nt][half*2+1] + bias[col+1];
                    v0 = 0.5f * v0 * (1.0f + erff(v0 * 0.70710678118654752f));
                    v1 = 0.5f * v1 * (1.0f + erff(v1 * 0.70710678118654752f));
                    __nv_bfloat16 h0, l0, h1, l1;
                    split2(v0, h0, l0);
                    split2(v1, h1, l1);
                    __nv_bfloat16 hh[2] = {h0, h1}, ll[2] = {l0, l1};
                    *(uint32_t*)(hrow + col) = *(uint32_t*)hh;
                    *(uint32_t*)(lrow + col) = *(uint32_t*)ll;
                }
            }
        }
    }
}

// ---------------- launch ----------------
extern "C" void kernel_launch(void* const* d_in, const int* in_sizes, int n_in,
                              void* d_out, int out_size) {
    const float* x      = (const float*)d_in[0];
    const float* wrf    = (const float*)d_in[1];
    const float* kqv_w  = (const float*)d_in[2];
    const float* kqv_b  = (const float*)d_in[3];
    const float* proj_w = (const float*)d_in[4];
    const float* proj_b = (const float*)d_in[5];
    const float* ln1_g  = (const float*)d_in[6];
    const float* ln1_b  = (const float*)d_in[7];
    const float* ln2_g  = (const float*)d_in[8];
    const float* ln2_b  = (const float*)d_in[9];
    const float* mlp_w1 = (const float*)d_in[10];
    const float* mlp_b1 = (const float*)d_in[11];
    const float* mlp_w2 = (const float*)d_in[12];
    const float* mlp_b2 = (const float*)d_in[13];
    float* out = (float*)d_out;

    float *p_h2, *p_v, *p_qp, *p_kp, *p_pk, *p_ps, *p_kptv, *p_ksum, *p_x1;
    __nv_bfloat16 *p_h2h, *p_h2l, *p_yh, *p_yl, *p_hidh, *p_hidl;
    __nv_bfloat16 *p_pwh, *p_pwl, *p_w1h, *p_w1l, *p_w2h, *p_w2l;
    cudaGetSymbolAddress((void**)&p_h2,   g_h2);
    cudaGetSymbolAddress((void**)&p_v,    g_v);
    cudaGetSymbolAddress((void**)&p_qp,   g_qp);
    cudaGetSymbolAddress((void**)&p_kp,   g_kp);
    cudaGetSymbolAddress((void**)&p_pk,   g_kptv_part);
    cudaGetSymbolAddress((void**)&p_ps,   g_ksum_part);
    cudaGetSymbolAddress((void**)&p_kptv, g_kptv);
    cudaGetSymbolAddress((void**)&p_ksum, g_ksum);
    cudaGetSymbolAddress((void**)&p_x1,   g_x1);
    cudaGetSymbolAddress((void**)&p_h2h,  g_h2h);
    cudaGetSymbolAddress((void**)&p_h2l,  g_h2l);
    cudaGetSymbolAddress((void**)&p_yh,   g_yh);
    cudaGetSymbolAddress((void**)&p_yl,   g_yl);
    cudaGetSymbolAddress((void**)&p_hidh, g_hidh);
    cudaGetSymbolAddress((void**)&p_hidl, g_hidl);
    cudaGetSymbolAddress((void**)&p_pwh,  g_pwh);
    cudaGetSymbolAddress((void**)&p_pwl,  g_pwl);
    cudaGetSymbolAddress((void**)&p_w1h,  g_w1h);
    cudaGetSymbolAddress((void**)&p_w1l,  g_w1l);
    cudaGetSymbolAddress((void**)&p_w2h,  g_w2h);
    cudaGetSymbolAddress((void**)&p_w2l,  g_w2l);

    const size_t k1_smem = (size_t)K1_SMEM_FLOATS * sizeof(float);
    cudaFuncSetAttribute(kqv_prm_kernel, cudaFuncAttributeMaxDynamicSharedMemorySize,
                         (int)k1_smem);
    cudaFuncSetAttribute(gemm_mma<0>, cudaFuncAttributeMaxDynamicSharedMemorySize, GEMM_SMEM);
    cudaFuncSetAttribute(gemm_mma<1>, cudaFuncAttributeMaxDynamicSharedMemorySize, GEMM_SMEM);

    // 0. weight splits
    cvt_split_kernel<<<(EMB*EMB/4 + 255)/256, 256>>>(proj_w, p_pwh, p_pwl, EMB*EMB/4);
    cvt_split_kernel<<<(HID*EMB/4 + 255)/256, 256>>>(mlp_w1, p_w1h, p_w1l, HID*EMB/4);
    cvt_split_kernel<<<(EMB*HID/4 + 255)/256, 256>>>(mlp_w2, p_w2h, p_w2l, EMB*HID/4);
    // 1. LN1
    ln_kernel<0><<<NTOK/8, 256>>>(x, ln1_g, ln1_b, p_h2, nullptr, nullptr);
    // 2. kqv + prm_exp
    kqv_prm_kernel<<<NTOK/8, 256, k1_smem>>>(p_h2, kqv_w, kqv_b, wrf, p_v, p_kp, p_qp);
    // 3-4. kptv/ksum reduction over T
    kpt_kernel<<<dim3(16, 64), 256>>>(p_v, p_kp, p_pk, p_ps);
    reduce_kernel<<<513, 256>>>(p_pk, p_ps, p_kptv, p_ksum);
    // 5. y (bf16 hi/lo planes)
    y_kernel<<<dim3(TQ/256, 64), 256>>>(p_qp, p_kptv, p_ksum, p_yh, p_yl);
    // 6. attn proj + residual -> x1 (fp32)
    gemm_mma<0><<<dim3(EMB/128, NTOK/128), 256, GEMM_SMEM>>>(
        p_yh, p_yl, p_pwh, p_pwl, proj_b, x, p_x1, nullptr, nullptr, EMB, EMB);
    // 7. LN2 -> bf16 hi/lo planes
    ln_kernel<1><<<NTOK/8, 256>>>(p_x1, ln2_g, ln2_b, nullptr, p_h2h, p_h2l);
    // 8. mlp1 + gelu -> hid hi/lo planes
    gemm_mma<1><<<dim3(HID/128, NTOK/128), 256, GEMM_SMEM>>>(
        p_h2h, p_h2l, p_w1h, p_w1l, mlp_b1, nullptr, nullptr, p_hidh, p_hidl, HID, EMB);
    // 9. mlp2 + residual -> out (fp32)
    gemm_mma<0><<<dim3(EMB/128, NTOK/128), 256, GEMM_SMEM>>>(
        p_hidh, p_hidl, p_w2h, p_w2l, mlp_b2, p_x1, out, nullptr, nullptr, EMB, HID);
}

// round 5
// speedup vs baseline: 2.0936x; 1.1855x over previous
#include <cuda_runtime.h>
#include <cuda_bf16.h>
#include <math.h>
#include <stdint.h>

// Problem constants
#define BQ 8
#define TQ 4096
#define NTOK (BQ*TQ)          // 32768 tokens
#define EMB 512
#define HEADS 8
#define ES 64
#define MF 32                 // random features
#define HID (4*EMB)           // 2048
#define LN_EPS 1e-5f

__device__ __forceinline__ uint32_t smem_to_u32(const void* smem_ptr) {
    uint32_t addr;
    asm("{ .reg .u64 tmp; cvta.to.shared.u64 tmp, %1; cvt.u32.u64 %0, tmp; }"
        : "=r"(addr) : "l"(smem_ptr));
    return addr;
}

__device__ __forceinline__ void cp_async16(uint32_t saddr, const void* gaddr) {
    asm volatile("cp.async.cg.shared.global [%0], [%1], 16;" :: "r"(saddr), "l"(gaddr));
}
#define CP_COMMIT() asm volatile("cp.async.commit_group;" ::: "memory")
#define CP_WAIT0()  asm volatile("cp.async.wait_group 0;" ::: "memory")
#define CP_WAIT1()  asm volatile("cp.async.wait_group 1;" ::: "memory")

__device__ __forceinline__ void ldsm_x4(uint32_t& r0, uint32_t& r1, uint32_t& r2, uint32_t& r3,
                                        uint32_t addr) {
    asm volatile("ldmatrix.sync.aligned.m8n8.x4.shared.b16 {%0,%1,%2,%3}, [%4];"
        : "=r"(r0), "=r"(r1), "=r"(r2), "=r"(r3) : "r"(addr));
}

__device__ __forceinline__ void mma_bf16(float* c, const uint32_t* a, const uint32_t* b) {
    asm volatile(
        "mma.sync.aligned.m16n8k16.row.col.f32.bf16.bf16.f32 "
        "{%0,%1,%2,%3}, {%4,%5,%6,%7}, {%8,%9}, {%0,%1,%2,%3};"
        : "+f"(c[0]), "+f"(c[1]), "+f"(c[2]), "+f"(c[3])
        : "r"(a[0]), "r"(a[1]), "r"(a[2]), "r"(a[3]), "r"(b[0]), "r"(b[1]));
}

__device__ __forceinline__ void split2(float x, __nv_bfloat16& h, __nv_bfloat16& l) {
    h = __float2bfloat16(x);
    l = __float2bfloat16(x - __bfloat162float(h));
}

// -------- scratch (device globals; no runtime allocation) --------
__device__ float g_h2[(size_t)NTOK*EMB];
__device__ float g_v[(size_t)NTOK*HEADS*ES];
__device__ float g_qp[(size_t)NTOK*HEADS*MF];
__device__ float g_kp[(size_t)NTOK*HEADS*MF];
__device__ float g_kptv_part[16*64*ES*MF];
__device__ float g_ksum_part[16*64*MF];
__device__ float g_kptv[64*ES*MF];
__device__ float g_ksum[64*MF];
__device__ float g_x1[(size_t)NTOK*EMB];
__device__ __align__(16) __nv_bfloat16 g_h2h[(size_t)NTOK*EMB], g_h2l[(size_t)NTOK*EMB];
__device__ __align__(16) __nv_bfloat16 g_yh[(size_t)NTOK*EMB],  g_yl[(size_t)NTOK*EMB];
__device__ __align__(16) __nv_bfloat16 g_hidh[(size_t)NTOK*HID], g_hidl[(size_t)NTOK*HID];
__device__ __align__(16) __nv_bfloat16 g_pwh[EMB*EMB],  g_pwl[EMB*EMB];
__device__ __align__(16) __nv_bfloat16 g_w1h[HID*EMB],  g_w1l[HID*EMB];
__device__ __align__(16) __nv_bfloat16 g_w2h[EMB*HID],  g_w2l[EMB*HID];

// ---------------- weight split conversion ----------------
__global__ void cvt_split_kernel(const float* __restrict__ w, __nv_bfloat16* __restrict__ hi,
                                 __nv_bfloat16* __restrict__ lo, int n4) {
    int i = blockIdx.x * 256 + threadIdx.x;
    if (i < n4) {
        float4 v = ((const float4*)w)[i];
        __nv_bfloat16 h[4], l[4];
        split2(v.x, h[0], l[0]); split2(v.y, h[1], l[1]);
        split2(v.z, h[2], l[2]); split2(v.w, h[3], l[3]);
        *(uint2*)(hi + (size_t)i*4) = *(uint2*)h;
        *(uint2*)(lo + (size_t)i*4) = *(uint2*)l;
    }
}

// ---------------- LayerNorm: warp per token ----------------
template<int MODE>
__global__ void ln_kernel(const float* __restrict__ x, const float* __restrict__ g,
                          const float* __restrict__ b, float* __restrict__ out,
                          __nv_bfloat16* __restrict__ ohi, __nv_bfloat16* __restrict__ olo) {
    int tok  = blockIdx.x * 8 + (threadIdx.x >> 5);
    int lane = threadIdx.x & 31;
    const float4* xr = (const float4*)(x + (size_t)tok * EMB);
    float4 v[4];
    float s = 0.f, sq = 0.f;
    #pragma unroll
    for (int i = 0; i < 4; i++) {
        v[i] = xr[lane + 32*i];
        s  += v[i].x + v[i].y + v[i].z + v[i].w;
        sq += v[i].x*v[i].x + v[i].y*v[i].y + v[i].z*v[i].z + v[i].w*v[i].w;
    }
    #pragma unroll
    for (int o = 16; o; o >>= 1) {
        s  += __shfl_xor_sync(0xffffffffu, s,  o);
        sq += __shfl_xor_sync(0xffffffffu, sq, o);
    }
    float mean = s * (1.0f/EMB);
    float var  = sq * (1.0f/EMB) - mean*mean;
    float rstd = rsqrtf(var + LN_EPS);
    const float4* g4 = (const float4*)g;
    const float4* b4 = (const float4*)b;
    #pragma unroll
    for (int i = 0; i < 4; i++) {
        float4 gg = g4[lane + 32*i], bb = b4[lane + 32*i];
        float4 o;
        o.x = (v[i].x - mean) * rstd * gg.x + bb.x;
        o.y = (v[i].y - mean) * rstd * gg.y + bb.y;
        o.z = (v[i].z - mean) * rstd * gg.z + bb.z;
        o.w = (v[i].w - mean) * rstd * gg.w + bb.w;
        if (MODE == 0) {
            ((float4*)(out + (size_t)tok * EMB))[lane + 32*i] = o;
        } else {
            size_t idx = (size_t)tok * EMB + (size_t)(lane + 32*i) * 4;
            __nv_bfloat16 h[4], l[4];
            split2(o.x, h[0], l[0]); split2(o.y, h[1], l[1]);
            split2(o.z, h[2], l[2]); split2(o.w, h[3], l[3]);
            *(uint2*)(ohi + idx) = *(uint2*)h;
            *(uint2*)(olo + idx) = *(uint2*)l;
        }
    }
}

// ---------------- kqv + prm_exp (8 tokens per block) ----------------
#define K1_SMEM_FLOATS (4096 + 12288 + 2048 + 192 + 1536 + 16)
__global__ void kqv_prm_kernel(const float* __restrict__ hN, const float* __restrict__ kqv_w,
                               const float* __restrict__ kqv_b, const float* __restrict__ wrf,
                               float* __restrict__ gv, float* __restrict__ gkp,
                               float* __restrict__ gqp) {
    extern __shared__ float sm[];
    float* sh_h  = sm;
    float* wk_t  = sm + 4096;
    float* wr_t  = wk_t + 12288;
    float* sbias = wr_t + 2048;
    float* skqv  = sbias + 192;
    float* sxd   = skqv + 1536;
    int tid = threadIdx.x;
    size_t t0 = (size_t)blockIdx.x * 8;

    {
        const float4* src = (const float4*)(hN + t0 * EMB);
        float4* dst = (float4*)sh_h;
        #pragma unroll
        for (int i = 0; i < 4; i++) dst[tid + 256*i] = src[tid + 256*i];
    }
    #pragma unroll
    for (int i = 0; i < 12; i++) {
        int j = tid + 256*i;
        int f = j >> 4, e0 = (j & 15) << 2;
        float4 w4 = ((const float4*)kqv_w)[j];
        wk_t[(e0+0)*192 + f] = w4.x;
        wk_t[(e0+1)*192 + f] = w4.y;
        wk_t[(e0+2)*192 + f] = w4.z;
        wk_t[(e0+3)*192 + f] = w4.w;
    }
    #pragma unroll
    for (int i = 0; i < 2; i++) {
        int j = tid + 256*i;
        int m = j >> 4, e0 = (j & 15) << 2;
        float4 w4 = ((const float4*)wrf)[j];
        wr_t[(e0+0)*32 + m] = w4.x;
        wr_t[(e0+1)*32 + m] = w4.y;
        wr_t[(e0+2)*32 + m] = w4.z;
        wr_t[(e0+3)*32 + m] = w4.w;
    }
    if (tid < 192) sbias[tid] = kqv_b[tid];
    __syncthreads();

    int fg = tid & 63, tg = tid >> 6;
    int f0 = fg * 3, tokA = tg * 2;

    for (int hd = 0; hd < HEADS; hd++) {
        float a00=0,a01=0,a10=0,a11=0,a20=0,a21=0;
        const float* hb = sh_h + hd * 64;
        #pragma unroll 8
        for (int e = 0; e < 64; e++) {
            float w0 = wk_t[e*192 + f0];
            float w1 = wk_t[e*192 + f0 + 1];
            float w2 = wk_t[e*192 + f0 + 2];
            float h0 = hb[tokA*512 + e];
            float h1 = hb[(tokA+1)*512 + e];
            a00 += w0*h0; a01 += w0*h1;
            a10 += w1*h0; a11 += w1*h1;
            a20 += w2*h0; a21 += w2*h1;
        }
        skqv[tokA*192 + f0 + 0] = a00 + sbias[f0+0];
        skqv[tokA*192 + f0 + 1] = a10 + sbias[f0+1];
        skqv[tokA*192 + f0 + 2] = a20 + sbias[f0+2];
        skqv[(tokA+1)*192 + f0 + 0] = a01 + sbias[f0+0];
        skqv[(tokA+1)*192 + f0 + 1] = a11 + sbias[f0+1];
        skqv[(tokA+1)*192 + f0 + 2] = a21 + sbias[f0+2];
        __syncthreads();

        #pragma unroll
        for (int i = 0; i < 2; i++) {
            int idx = tid + 256*i;
            int tok = idx >> 6, e = idx & 63;
            gv[(((t0 + tok) * HEADS) + hd) * ES + e] = skqv[tok*192 + 128 + e];
        }
        if (tid < 16) {
            int tok = tid >> 1, which = tid & 1;
            const float* z = skqv + tok*192 + which*64;
            float s = 0.f;
            #pragma unroll 8
            for (int e = 0; e < 64; e++) { float zz = z[e]; s += zz*zz; }
            sxd[tid] = 0.5f * s;
        }
        __syncthreads();

        #pragma unroll
        for (int i = 0; i < 2; i++) {
            int idx = tid + 256*i;
            int m = idx & 31, which = (idx >> 5) & 1, tok = idx >> 6;
            const float* z = skqv + tok*192 + which*64;
            float a = 0.f;
            #pragma unroll 8
            for (int e = 0; e < 64; e++) a += z[e] * wr_t[e*32 + m];
            float val = expf(a - sxd[tok*2 + which]) * 0.17677669529663689f;
            float* dst = which ? gqp : gkp;
            dst[(((t0 + tok) * HEADS) + hd) * MF + m] = val;
        }
        __syncthreads();
    }
}

// ---------------- kptv / ksum partial reduction over T ----------------
__global__ void kpt_kernel(const float* __restrict__ gv, const float* __restrict__ gkp,
                           float* __restrict__ part_kptv, float* __restrict__ part_ksum) {
    int chunk = blockIdx.x;
    int bh = blockIdx.y;
    int b = bh >> 3, h = bh & 7;
    __shared__ float sv[16][64];
    __shared__ float skp[16][32];
    int tid = threadIdx.x, lane = tid & 31, wid = tid >> 5;
    float acc[8] = {0,0,0,0,0,0,0,0};
    float ks = 0.f;
    int t0 = chunk * 256;
    for (int st = 0; st < 16; st++) {
        int s0 = t0 + st * 16;
        __syncthreads();
        #pragma unroll
        for (int i = 0; i < 4; i++) {
            int idx = tid + 256*i;
            int s = idx >> 6, e = idx & 63;
            sv[s][e] = gv[((((size_t)b*TQ + s0 + s) * HEADS) + h) * ES + e];
        }
        #pragma unroll
        for (int i = 0; i < 2; i++) {
            int idx = tid + 256*i;
            int s = idx >> 5, m = idx & 31;
            skp[s][m] = gkp[((((size_t)b*TQ + s0 + s) * HEADS) + h) * MF + m];
        }
        __syncthreads();
        #pragma unroll
        for (int s = 0; s < 16; s++) {
            float kv = skp[s][lane];
            float4 va = *(const float4*)&sv[s][wid*8];
            float4 vb = *(const float4*)&sv[s][wid*8 + 4];
            acc[0] += va.x*kv; acc[1] += va.y*kv; acc[2] += va.z*kv; acc[3] += va.w*kv;
            acc[4] += vb.x*kv; acc[5] += vb.y*kv; acc[6] += vb.z*kv; acc[7] += vb.w*kv;
            if (wid == 0) ks += kv;
        }
    }
    size_t base = ((size_t)(chunk*64 + bh)) * (ES*MF);
    #pragma unroll
    for (int j = 0; j < 8; j++)
        part_kptv[base + (wid*8 + j)*MF + lane] = acc[j];
    if (wid == 0) part_ksum[(chunk*64 + bh)*MF + lane] = ks;
}

__global__ void reduce_kernel(const float* __restrict__ pk, const float* __restrict__ ps,
                              float* __restrict__ kptv, float* __restrict__ ksum) {
    int bid = blockIdx.x;
    if (bid < 512) {
        int idx = bid * 256 + threadIdx.x;
        int bh = idx >> 11;
        float s = 0.f;
        #pragma unroll
        for (int c = 0; c < 16; c++) s += pk[((size_t)(c*64 + bh)) * 2048 + (idx & 2047)];
        kptv[idx] = s;
    } else {
        #pragma unroll
        for (int j = 0; j < 8; j++) {
            int idx = threadIdx.x * 8 + j;
            int bh = idx >> 5, m = idx & 31;
            float s = 0.f;
            #pragma unroll
            for (int c = 0; c < 16; c++) s += ps[(c*64 + bh)*MF + m];
            ksum[idx] = s;
        }
    }
}

// ---------------- y = (qp . kptv) / D  -> bf16 hi/lo planes ----------------
__global__ void y_kernel(const float* __restrict__ gqp, const float* __restrict__ kptv,
                         const float* __restrict__ ksum, __nv_bfloat16* __restrict__ yh,
                         __nv_bfloat16* __restrict__ yl) {
    int bh = blockIdx.y, b = bh >> 3, h = bh & 7;
    __shared__ float sk[64*33];
    __shared__ float sks[32];
    int tid = threadIdx.x, lane = tid & 31, wid = tid >> 5;
    #pragma unroll
    for (int i = 0; i < 8; i++) {
        int idx = tid + 256*i;
        sk[(idx >> 5)*33 + (idx & 31)] = kptv[(size_t)bh*2048 + idx];
    }
    if (tid < 32) sks[tid] = ksum[bh*32 + tid];
    __syncthreads();
    float ksv = sks[lane];
    for (int it = 0; it < 32; it++) {
        int t = blockIdx.x * 256 + wid * 32 + it;
        float qpv = gqp[((((size_t)b*TQ + t) * HEADS) + h) * MF + lane];
        float d = qpv * ksv;
        #pragma unroll
        for (int o = 16; o; o >>= 1) d += __shfl_xor_sync(0xffffffffu, d, o);
        float a0 = 0.f, a1 = 0.f;
        #pragma unroll
        for (int m = 0; m < 32; m++) {
            float qm = __shfl_sync(0xffffffffu, qpv, m);
            a0 += qm * sk[lane*33 + m];
            a1 += qm * sk[(lane+32)*33 + m];
        }
        float inv = 1.0f / d;
        size_t off = ((size_t)b*TQ + t) * EMB + h * ES;
        float v0 = a0 * inv, v1 = a1 * inv;
        __nv_bfloat16 h0, l0, h1, l1;
        split2(v0, h0, l0);
        split2(v1, h1, l1);
        yh[off + lane]      = h0;  yl[off + lane]      = l0;
        yh[off + lane + 32] = h1;  yl[off + lane + 32] = l1;
    }
}

// ============== mma.sync bf16-split GEMM: C = A(MxK) * W(NxK)^T + epilogue ==============
// 128x128 CTA tile, 8 warps (4m x 2n), warp tile 32x64, chunk K=32, cp.async double buffer.
// Packed 64B rows + XOR swizzle: chunk' = chunk ^ ((row>>1)&3). All 16B-aligned,
// ldmatrix 8-row tiles conflict-free. 2 CTAs/SM.
#define PLANE_BYTES 8192                  // 128 rows x 64B
#define BUF_BYTES (4*PLANE_BYTES)         // 32768
#define GEMM_SMEM (2*BUF_BYTES)           // 65536

#define SWZ_ADDR(base, row, chunk) \
    ((base) + (uint32_t)(row)*64u + (uint32_t)(((chunk) ^ (((row)>>1)&3)) << 4))

template<int EPI>
__global__ __launch_bounds__(256, 2)
void gemm_mma(const __nv_bfloat16* __restrict__ Ah, const __nv_bfloat16* __restrict__ Al,
              const __nv_bfloat16* __restrict__ Bh, const __nv_bfloat16* __restrict__ Bl,
              const float* __restrict__ bias, const float* __restrict__ res,
              float* __restrict__ Cf, __nv_bfloat16* __restrict__ Chi,
              __nv_bfloat16* __restrict__ Clo, int N, int K) {
    extern __shared__ char gsm[];
    uint32_t sb = smem_to_u32(gsm);
    int tid = threadIdx.x, lane = tid & 31, wid = tid >> 5;
    int rowBase = blockIdx.y * 128, colBase = blockIdx.x * 128;

    int wm = wid & 3, wn = wid >> 2;      // 4x2 warp grid
    int m0 = wm * 32, n0 = wn * 64;

    float acc[2][8][4];
    #pragma unroll
    for (int i = 0; i < 2; i++)
        #pragma unroll
        for (int j = 0; j < 8; j++)
            #pragma unroll
            for (int q = 0; q < 4; q++) acc[i][j][q] = 0.f;

    // per-lane ldmatrix row/chunk components
    int arow_l = (lane & 15);             // + m0 + mt*16
    int acb    = (lane >> 4);             // chunk bit: + ks*2
    int brow_l = (lane & 7) + ((lane >> 4) << 3);  // + n0 + ng*16
    int bcb    = (lane >> 3) & 1;

    // loader: 4 planes x 128 rows x 64B, 8 x 16B transfers per thread
    auto load_chunk = [&](int buf, int k0) {
        uint32_t sbase = sb + buf * BUF_BYTES;
        int row = tid >> 1, c0 = (tid & 1) * 2;   // chunks c0, c0+1
        uint32_t so  = SWZ_ADDR(sbase, row, c0);
        uint32_t so1 = SWZ_ADDR(sbase, row, c0 + 1);
        size_t goA = (size_t)(rowBase + row) * K + k0 + c0 * 8;
        size_t goB = (size_t)(colBase + row) * K + k0 + c0 * 8;
        cp_async16(so,                     Ah + goA);
        cp_async16(so1,                    Ah + goA + 8);
        cp_async16(PLANE_BYTES   + so,     Al + goA);
        cp_async16(PLANE_BYTES   + so1,    Al + goA + 8);
        cp_async16(2*PLANE_BYTES + so,     Bh + goB);
        cp_async16(2*PLANE_BYTES + so1,    Bh + goB + 8);
        cp_async16(3*PLANE_BYTES + so,     Bl + goB);
        cp_async16(3*PLANE_BYTES + so1,    Bl + goB + 8);
    };

    int NC = K >> 5;
    load_chunk(0, 0);
    CP_COMMIT();

    for (int c = 0; c < NC; c++) {
        int buf = c & 1;
        if (c + 1 < NC) {
            load_chunk(buf ^ 1, (c + 1) << 5);
            CP_COMMIT();
            CP_WAIT1();
        } else {
            CP_WAIT0();
        }
        __syncthreads();

        uint32_t pA = sb + buf * BUF_BYTES;
        #pragma unroll
        for (int ks = 0; ks < 2; ks++) {
            uint32_t ah[2][4], al[2][4];
            #pragma unroll
            for (int mt = 0; mt < 2; mt++) {
                int ar = m0 + mt * 16 + arow_l;
                uint32_t ad = SWZ_ADDR(pA, ar, ks * 2 + acb);
                ldsm_x4(ah[mt][0], ah[mt][1], ah[mt][2], ah[mt][3], ad);
                ldsm_x4(al[mt][0], al[mt][1], al[mt][2], al[mt][3], ad + PLANE_BYTES);
            }
            #pragma unroll
            for (int ng = 0; ng < 4; ng++) {
                int br = n0 + ng * 16 + brow_l;
                uint32_t bd = SWZ_ADDR(pA + 2*PLANE_BYTES, br, ks * 2 + bcb);
                uint32_t bh2[2][2], bl2[2][2];
                ldsm_x4(bh2[0][0], bh2[0][1], bh2[1][0], bh2[1][1], bd);
                ldsm_x4(bl2[0][0], bl2[0][1], bl2[1][0], bl2[1][1], bd + PLANE_BYTES);
                #pragma unroll
                for (int mt = 0; mt < 2; mt++)
                    #pragma unroll
                    for (int j = 0; j < 2; j++) {
                        int nt = 2*ng + j;
                        mma_bf16(acc[mt][nt], ah[mt], bh2[j]);
                        mma_bf16(acc[mt][nt], ah[mt], bl2[j]);
                        mma_bf16(acc[mt][nt], al[mt], bh2[j]);
                    }
            }
        }
        __syncthreads();
    }

    // ---- epilogue ----
    int rbase = rowBase + m0 + (lane >> 2);
    int cbase = colBase + n0 + (lane & 3) * 2;
    #pragma unroll
    for (int mt = 0; mt < 2; mt++) {
        #pragma unroll
        for (int half = 0; half < 2; half++) {
            int row = rbase + mt * 16 + half * 8;
            if (EPI == 0) {
                float* crow = Cf + (size_t)row * N;
                const float* rrow = res + (size_t)row * N;
                #pragma unroll
                for (int nt = 0; nt < 8; nt++) {
                    int col = cbase + nt * 8;
                    float2 o;
                    o.x = acc[mt][nt][half*2+0] + bias[col]   + rrow[col];
                    o.y = acc[mt][nt][half*2+1] + bias[col+1] + rrow[col+1];
                    *(float2*)(crow + col) = o;
                }
            } else {
                __nv_bfloat16* hrow = Chi + (size_t)row * N;
                __nv_bfloat16* lrow = Clo + (size_t)row * N;
                #pragma unroll
                for (int nt = 0; nt < 8; nt++) {
                    int col = cbase + nt * 8;
                    float v0 = acc[mt][nt][half*2+0] + bias[col];
                    float v1 = acc[mt][nt][half*2+1] + bias[col+1];
                    v0 = 0.5f * v0 * (1.0f + erff(v0 * 0.70710678118654752f));
                    v1 = 0.5f * v1 * (1.0f + erff(v1 * 0.70710678118654752f));
                    __nv_bfloat16 h0, l0, h1, l1;
                    split2(v0, h0, l0);
                    split2(v1, h1, l1);
                    __nv_bfloat16 hh[2] = {h0, h1}, ll[2] = {l0, l1};
                    *(uint32_t*)(hrow + col) = *(uint32_t*)hh;
                    *(uint32_t*)(lrow + col) = *(uint32_t*)ll;
                }
            }
        }
    }
}

// ---------------- launch ----------------
extern "C" void kernel_launch(void* const* d_in, const int* in_sizes, int n_in,
                              void* d_out, int out_size) {
    const float* x      = (const float*)d_in[0];
    const float* wrf    = (const float*)d_in[1];
    const float* kqv_w  = (const float*)d_in[2];
    const float* kqv_b  = (const float*)d_in[3];
    const float* proj_w = (const float*)d_in[4];
    const float* proj_b = (const float*)d_in[5];
    const float* ln1_g  = (const float*)d_in[6];
    const float* ln1_b  = (const float*)d_in[7];
    const float* ln2_g  = (const float*)d_in[8];
    const float* ln2_b  = (const float*)d_in[9];
    const float* mlp_w1 = (const float*)d_in[10];
    const float* mlp_b1 = (const float*)d_in[11];
    const float* mlp_w2 = (const float*)d_in[12];
    const float* mlp_b2 = (const float*)d_in[13];
    float* out = (float*)d_out;

    float *p_h2, *p_v, *p_qp, *p_kp, *p_pk, *p_ps, *p_kptv, *p_ksum, *p_x1;
    __nv_bfloat16 *p_h2h, *p_h2l, *p_yh, *p_yl, *p_hidh, *p_hidl;
    __nv_bfloat16 *p_pwh, *p_pwl, *p_w1h, *p_w1l, *p_w2h, *p_w2l;
    cudaGetSymbolAddress((void**)&p_h2,   g_h2);
    cudaGetSymbolAddress((void**)&p_v,    g_v);
    cudaGetSymbolAddress((void**)&p_qp,   g_qp);
    cudaGetSymbolAddress((void**)&p_kp,   g_kp);
    cudaGetSymbolAddress((void**)&p_pk,   g_kptv_part);
    cudaGetSymbolAddress((void**)&p_ps,   g_ksum_part);
    cudaGetSymbolAddress((void**)&p_kptv, g_kptv);
    cudaGetSymbolAddress((void**)&p_ksum, g_ksum);
    cudaGetSymbolAddress((void**)&p_x1,   g_x1);
    cudaGetSymbolAddress((void**)&p_h2h,  g_h2h);
    cudaGetSymbolAddress((void**)&p_h2l,  g_h2l);
    cudaGetSymbolAddress((void**)&p_yh,   g_yh);
    cudaGetSymbolAddress((void**)&p_yl,   g_yl);
    cudaGetSymbolAddress((void**)&p_hidh, g_hidh);
    cudaGetSymbolAddress((void**)&p_hidl, g_hidl);
    cudaGetSymbolAddress((void**)&p_pwh,  g_pwh);
    cudaGetSymbolAddress((void**)&p_pwl,  g_pwl);
    cudaGetSymbolAddress((void**)&p_w1h,  g_w1h);
    cudaGetSymbolAddress((void**)&p_w1l,  g_w1l);
    cudaGetSymbolAddress((void**)&p_w2h,  g_w2h);
    cudaGetSymbolAddress((void**)&p_w2l,  g_w2l);

    const size_t k1_smem = (size_t)K1_SMEM_FLOATS * sizeof(float);
    cudaFuncSetAttribute(kqv_prm_kernel, cudaFuncAttributeMaxDynamicSharedMemorySize,
                         (int)k1_smem);
    cudaFuncSetAttribute(gemm_mma<0>, cudaFuncAttributeMaxDynamicSharedMemorySize, GEMM_SMEM);
    cudaFuncSetAttribute(gemm_mma<1>, cudaFuncAttributeMaxDynamicSharedMemorySize, GEMM_SMEM);

    // 0. weight splits
    cvt_split_kernel<<<(EMB*EMB/4 + 255)/256, 256>>>(proj_w, p_pwh, p_pwl, EMB*EMB/4);
    cvt_split_kernel<<<(HID*EMB/4 + 255)/256, 256>>>(mlp_w1, p_w1h, p_w1l, HID*EMB/4);
    cvt_split_kernel<<<(EMB*HID/4 + 255)/256, 256>>>(mlp_w2, p_w2h, p_w2l, EMB*HID/4);
    // 1. LN1
    ln_kernel<0><<<NTOK/8, 256>>>(x, ln1_g, ln1_b, p_h2, nullptr, nullptr);
    // 2. kqv + prm_exp
    kqv_prm_kernel<<<NTOK/8, 256, k1_smem>>>(p_h2, kqv_w, kqv_b, wrf, p_v, p_kp, p_qp);
    // 3-4. kptv/ksum reduction over T
    kpt_kernel<<<dim3(16, 64), 256>>>(p_v, p_kp, p_pk, p_ps);
    reduce_kernel<<<513, 256>>>(p_pk, p_ps, p_kptv, p_ksum);
    // 5. y (bf16 hi/lo planes)
    y_kernel<<<dim3(TQ/256, 64), 256>>>(p_qp, p_kptv, p_ksum, p_yh, p_yl);
    // 6. attn proj + residual -> x1 (fp32)
    gemm_mma<0><<<dim3(EMB/128, NTOK/128), 256, GEMM_SMEM>>>(
        p_yh, p_yl, p_pwh, p_pwl, proj_b, x, p_x1, nullptr, nullptr, EMB, EMB);
    // 7. LN2 -> bf16 hi/lo planes
    ln_kernel<1><<<NTOK/8, 256>>>(p_x1, ln2_g, ln2_b, nullptr, p_h2h, p_h2l);
    // 8. mlp1 + gelu -> hid hi/lo planes
    gemm_mma<1><<<dim3(HID/128, NTOK/128), 256, GEMM_SMEM>>>(
        p_h2h, p_h2l, p_w1h, p_w1l, mlp_b1, nullptr, nullptr, p_hidh, p_hidl, HID, EMB);
    // 9. mlp2 + residual -> out (fp32)
    gemm_mma<0><<<dim3(EMB/128, NTOK/128), 256, GEMM_SMEM>>>(
        p_hidh, p_hidl, p_w2h, p_w2l, mlp_b2, p_x1, out, nullptr, nullptr, EMB, HID);
}

// round 6
// speedup vs baseline: 2.5593x; 1.2225x over previous
#include <cuda_runtime.h>
#include <cuda_fp16.h>
#include <math.h>
#include <stdint.h>

// Problem constants
#define BQ 8
#define TQ 4096
#define NTOK (BQ*TQ)          // 32768 tokens
#define EMB 512
#define HEADS 8
#define ES 64
#define MF 32                 // random features
#define HID (4*EMB)           // 2048
#define LN_EPS 1e-5f

__device__ __forceinline__ uint32_t smem_to_u32(const void* smem_ptr) {
    uint32_t addr;
    asm("{ .reg .u64 tmp; cvta.to.shared.u64 tmp, %1; cvt.u32.u64 %0, tmp; }"
        : "=r"(addr) : "l"(smem_ptr));
    return addr;
}

__device__ __forceinline__ void cp_async16(uint32_t saddr, const void* gaddr) {
    asm volatile("cp.async.cg.shared.global [%0], [%1], 16;" :: "r"(saddr), "l"(gaddr));
}
#define CP_COMMIT() asm volatile("cp.async.commit_group;" ::: "memory")
#define CP_WAIT0()  asm volatile("cp.async.wait_group 0;" ::: "memory")
#define CP_WAIT1()  asm volatile("cp.async.wait_group 1;" ::: "memory")

__device__ __forceinline__ void ldsm_x4(uint32_t& r0, uint32_t& r1, uint32_t& r2, uint32_t& r3,
                                        uint32_t addr) {
    asm volatile("ldmatrix.sync.aligned.m8n8.x4.shared.b16 {%0,%1,%2,%3}, [%4];"
        : "=r"(r0), "=r"(r1), "=r"(r2), "=r"(r3) : "r"(addr));
}

__device__ __forceinline__ void mma_f16(float* c, const uint32_t* a, const uint32_t* b) {
    asm volatile(
        "mma.sync.aligned.m16n8k16.row.col.f32.f16.f16.f32 "
        "{%0,%1,%2,%3}, {%4,%5,%6,%7}, {%8,%9}, {%0,%1,%2,%3};"
        : "+f"(c[0]), "+f"(c[1]), "+f"(c[2]), "+f"(c[3])
        : "r"(a[0]), "r"(a[1]), "r"(a[2]), "r"(a[3]), "r"(b[0]), "r"(b[1]));
}

__device__ __forceinline__ void split2h(float x, __half& h, __half& l) {
    h = __float2half(x);
    l = __float2half(x - __half2float(h));
}

// -------- scratch (device globals; no runtime allocation) --------
__device__ float g_h2[(size_t)NTOK*EMB];
__device__ float g_v[(size_t)NTOK*HEADS*ES];
__device__ float g_qp[(size_t)NTOK*HEADS*MF];
__device__ float g_kp[(size_t)NTOK*HEADS*MF];
__device__ float g_kptv_part[16*64*ES*MF];
__device__ float g_ksum_part[16*64*MF];
__device__ float g_kptv[64*ES*MF];
__device__ float g_ksum[64*MF];
__device__ float g_x1[(size_t)NTOK*EMB];
// fp16 planes: activations hi/lo, weights hi only
__device__ __align__(16) __half g_h2h[(size_t)NTOK*EMB], g_h2l[(size_t)NTOK*EMB];
__device__ __align__(16) __half g_yh[(size_t)NTOK*EMB],  g_yl[(size_t)NTOK*EMB];
__device__ __align__(16) __half g_hidh[(size_t)NTOK*HID], g_hidl[(size_t)NTOK*HID];
__device__ __align__(16) __half g_pwh[EMB*EMB];
__device__ __align__(16) __half g_w1h[HID*EMB];
__device__ __align__(16) __half g_w2h[EMB*HID];

// ---------------- weight fp16 conversion (round only) ----------------
__global__ void cvt_h_kernel(const float* __restrict__ w, __half* __restrict__ hi, int n4) {
    int i = blockIdx.x * 256 + threadIdx.x;
    if (i < n4) {
        float4 v = ((const float4*)w)[i];
        __half h[4];
        h[0] = __float2half(v.x); h[1] = __float2half(v.y);
        h[2] = __float2half(v.z); h[3] = __float2half(v.w);
        *(uint2*)(hi + (size_t)i*4) = *(uint2*)h;
    }
}

// ---------------- LayerNorm: warp per token ----------------
template<int MODE>
__global__ void ln_kernel(const float* __restrict__ x, const float* __restrict__ g,
                          const float* __restrict__ b, float* __restrict__ out,
                          __half* __restrict__ ohi, __half* __restrict__ olo) {
    int tok  = blockIdx.x * 8 + (threadIdx.x >> 5);
    int lane = threadIdx.x & 31;
    const float4* xr = (const float4*)(x + (size_t)tok * EMB);
    float4 v[4];
    float s = 0.f, sq = 0.f;
    #pragma unroll
    for (int i = 0; i < 4; i++) {
        v[i] = xr[lane + 32*i];
        s  += v[i].x + v[i].y + v[i].z + v[i].w;
        sq += v[i].x*v[i].x + v[i].y*v[i].y + v[i].z*v[i].z + v[i].w*v[i].w;
    }
    #pragma unroll
    for (int o = 16; o; o >>= 1) {
        s  += __shfl_xor_sync(0xffffffffu, s,  o);
        sq += __shfl_xor_sync(0xffffffffu, sq, o);
    }
    float mean = s * (1.0f/EMB);
    float var  = sq * (1.0f/EMB) - mean*mean;
    float rstd = rsqrtf(var + LN_EPS);
    const float4* g4 = (const float4*)g;
    const float4* b4 = (const float4*)b;
    #pragma unroll
    for (int i = 0; i < 4; i++) {
        float4 gg = g4[lane + 32*i], bb = b4[lane + 32*i];
        float4 o;
        o.x = (v[i].x - mean) * rstd * gg.x + bb.x;
        o.y = (v[i].y - mean) * rstd * gg.y + bb.y;
        o.z = (v[i].z - mean) * rstd * gg.z + bb.z;
        o.w = (v[i].w - mean) * rstd * gg.w + bb.w;
        if (MODE == 0) {
            ((float4*)(out + (size_t)tok * EMB))[lane + 32*i] = o;
        } else {
            size_t idx = (size_t)tok * EMB + (size_t)(lane + 32*i) * 4;
            __half h[4], l[4];
            split2h(o.x, h[0], l[0]); split2h(o.y, h[1], l[1]);
            split2h(o.z, h[2], l[2]); split2h(o.w, h[3], l[3]);
            *(uint2*)(ohi + idx) = *(uint2*)h;
            *(uint2*)(olo + idx) = *(uint2*)l;
        }
    }
}

// ---------------- kqv + prm_exp (8 tokens per block) ----------------
#define K1_SMEM_FLOATS (4096 + 12288 + 2048 + 192 + 1536 + 16)
__global__ void kqv_prm_kernel(const float* __restrict__ hN, const float* __restrict__ kqv_w,
                               const float* __restrict__ kqv_b, const float* __restrict__ wrf,
                               float* __restrict__ gv, float* __restrict__ gkp,
                               float* __restrict__ gqp) {
    extern __shared__ float sm[];
    float* sh_h  = sm;
    float* wk_t  = sm + 4096;
    float* wr_t  = wk_t + 12288;
    float* sbias = wr_t + 2048;
    float* skqv  = sbias + 192;
    float* sxd   = skqv + 1536;
    int tid = threadIdx.x;
    size_t t0 = (size_t)blockIdx.x * 8;

    {
        const float4* src = (const float4*)(hN + t0 * EMB);
        float4* dst = (float4*)sh_h;
        #pragma unroll
        for (int i = 0; i < 4; i++) dst[tid + 256*i] = src[tid + 256*i];
    }
    #pragma unroll
    for (int i = 0; i < 12; i++) {
        int j = tid + 256*i;
        int f = j >> 4, e0 = (j & 15) << 2;
        float4 w4 = ((const float4*)kqv_w)[j];
        wk_t[(e0+0)*192 + f] = w4.x;
        wk_t[(e0+1)*192 + f] = w4.y;
        wk_t[(e0+2)*192 + f] = w4.z;
        wk_t[(e0+3)*192 + f] = w4.w;
    }
    #pragma unroll
    for (int i = 0; i < 2; i++) {
        int j = tid + 256*i;
        int m = j >> 4, e0 = (j & 15) << 2;
        float4 w4 = ((const float4*)wrf)[j];
        wr_t[(e0+0)*32 + m] = w4.x;
        wr_t[(e0+1)*32 + m] = w4.y;
        wr_t[(e0+2)*32 + m] = w4.z;
        wr_t[(e0+3)*32 + m] = w4.w;
    }
    if (tid < 192) sbias[tid] = kqv_b[tid];
    __syncthreads();

    int fg = tid & 63, tg = tid >> 6;
    int f0 = fg * 3, tokA = tg * 2;

    for (int hd = 0; hd < HEADS; hd++) {
        float a00=0,a01=0,a10=0,a11=0,a20=0,a21=0;
        const float* hb = sh_h + hd * 64;
        #pragma unroll 8
        for (int e = 0; e < 64; e++) {
            float w0 = wk_t[e*192 + f0];
            float w1 = wk_t[e*192 + f0 + 1];
            float w2 = wk_t[e*192 + f0 + 2];
            float h0 = hb[tokA*512 + e];
            float h1 = hb[(tokA+1)*512 + e];
            a00 += w0*h0; a01 += w0*h1;
            a10 += w1*h0; a11 += w1*h1;
            a20 += w2*h0; a21 += w2*h1;
        }
        skqv[tokA*192 + f0 + 0] = a00 + sbias[f0+0];
        skqv[tokA*192 + f0 + 1] = a10 + sbias[f0+1];
        skqv[tokA*192 + f0 + 2] = a20 + sbias[f0+2];
        skqv[(tokA+1)*192 + f0 + 0] = a01 + sbias[f0+0];
        skqv[(tokA+1)*192 + f0 + 1] = a11 + sbias[f0+1];
        skqv[(tokA+1)*192 + f0 + 2] = a21 + sbias[f0+2];
        __syncthreads();

        #pragma unroll
        for (int i = 0; i < 2; i++) {
            int idx = tid + 256*i;
            int tok = idx >> 6, e = idx & 63;
            gv[(((t0 + tok) * HEADS) + hd) * ES + e] = skqv[tok*192 + 128 + e];
        }
        if (tid < 16) {
            int tok = tid >> 1, which = tid & 1;
            const float* z = skqv + tok*192 + which*64;
            float s = 0.f;
            #pragma unroll 8
            for (int e = 0; e < 64; e++) { float zz = z[e]; s += zz*zz; }
            sxd[tid] = 0.5f * s;
        }
        __syncthreads();

        #pragma unroll
        for (int i = 0; i < 2; i++) {
            int idx = tid + 256*i;
            int m = idx & 31, which = (idx >> 5) & 1, tok = idx >> 6;
            const float* z = skqv + tok*192 + which*64;
            float a = 0.f;
            #pragma unroll 8
            for (int e = 0; e < 64; e++) a += z[e] * wr_t[e*32 + m];
            float val = expf(a - sxd[tok*2 + which]) * 0.17677669529663689f;
            float* dst = which ? gqp : gkp;
            dst[(((t0 + tok) * HEADS) + hd) * MF + m] = val;
        }
        __syncthreads();
    }
}

// ---------------- kptv / ksum partial reduction over T ----------------
__global__ void kpt_kernel(const float* __restrict__ gv, const float* __restrict__ gkp,
                           float* __restrict__ part_kptv, float* __restrict__ part_ksum) {
    int chunk = blockIdx.x;
    int bh = blockIdx.y;
    int b = bh >> 3, h = bh & 7;
    __shared__ float sv[16][64];
    __shared__ float skp[16][32];
    int tid = threadIdx.x, lane = tid & 31, wid = tid >> 5;
    float acc[8] = {0,0,0,0,0,0,0,0};
    float ks = 0.f;
    int t0 = chunk * 256;
    for (int st = 0; st < 16; st++) {
        int s0 = t0 + st * 16;
        __syncthreads();
        #pragma unroll
        for (int i = 0; i < 4; i++) {
            int idx = tid + 256*i;
            int s = idx >> 6, e = idx & 63;
            sv[s][e] = gv[((((size_t)b*TQ + s0 + s) * HEADS) + h) * ES + e];
        }
        #pragma unroll
        for (int i = 0; i < 2; i++) {
            int idx = tid + 256*i;
            int s = idx >> 5, m = idx & 31;
            skp[s][m] = gkp[((((size_t)b*TQ + s0 + s) * HEADS) + h) * MF + m];
        }
        __syncthreads();
        #pragma unroll
        for (int s = 0; s < 16; s++) {
            float kv = skp[s][lane];
            float4 va = *(const float4*)&sv[s][wid*8];
            float4 vb = *(const float4*)&sv[s][wid*8 + 4];
            acc[0] += va.x*kv; acc[1] += va.y*kv; acc[2] += va.z*kv; acc[3] += va.w*kv;
            acc[4] += vb.x*kv; acc[5] += vb.y*kv; acc[6] += vb.z*kv; acc[7] += vb.w*kv;
            if (wid == 0) ks += kv;
        }
    }
    size_t base = ((size_t)(chunk*64 + bh)) * (ES*MF);
    #pragma unroll
    for (int j = 0; j < 8; j++)
        part_kptv[base + (wid*8 + j)*MF + lane] = acc[j];
    if (wid == 0) part_ksum[(chunk*64 + bh)*MF + lane] = ks;
}

__global__ void reduce_kernel(const float* __restrict__ pk, const float* __restrict__ ps,
                              float* __restrict__ kptv, float* __restrict__ ksum) {
    int bid = blockIdx.x;
    if (bid < 512) {
        int idx = bid * 256 + threadIdx.x;
        int bh = idx >> 11;
        float s = 0.f;
        #pragma unroll
        for (int c = 0; c < 16; c++) s += pk[((size_t)(c*64 + bh)) * 2048 + (idx & 2047)];
        kptv[idx] = s;
    } else {
        #pragma unroll
        for (int j = 0; j < 8; j++) {
            int idx = threadIdx.x * 8 + j;
            int bh = idx >> 5, m = idx & 31;
            float s = 0.f;
            #pragma unroll
            for (int c = 0; c < 16; c++) s += ps[(c*64 + bh)*MF + m];
            ksum[idx] = s;
        }
    }
}

// ---------------- y = (qp . kptv) / D  -> fp16 hi/lo planes ----------------
__global__ void y_kernel(const float* __restrict__ gqp, const float* __restrict__ kptv,
                         const float* __restrict__ ksum, __half* __restrict__ yh,
                         __half* __restrict__ yl) {
    int bh = blockIdx.y, b = bh >> 3, h = bh & 7;
    __shared__ float sk[64*33];
    __shared__ float sks[32];
    int tid = threadIdx.x, lane = tid & 31, wid = tid >> 5;
    #pragma unroll
    for (int i = 0; i < 8; i++) {
        int idx = tid + 256*i;
        sk[(idx >> 5)*33 + (idx & 31)] = kptv[(size_t)bh*2048 + idx];
    }
    if (tid < 32) sks[tid] = ksum[bh*32 + tid];
    __syncthreads();
    float ksv = sks[lane];
    for (int it = 0; it < 32; it++) {
        int t = blockIdx.x * 256 + wid * 32 + it;
        float qpv = gqp[((((size_t)b*TQ + t) * HEADS) + h) * MF + lane];
        float d = qpv * ksv;
        #pragma unroll
        for (int o = 16; o; o >>= 1) d += __shfl_xor_sync(0xffffffffu, d, o);
        float a0 = 0.f, a1 = 0.f;
        #pragma unroll
        for (int m = 0; m < 32; m++) {
            float qm = __shfl_sync(0xffffffffu, qpv, m);
            a0 += qm * sk[lane*33 + m];
            a1 += qm * sk[(lane+32)*33 + m];
        }
        float inv = 1.0f / d;
        size_t off = ((size_t)b*TQ + t) * EMB + h * ES;
        float v0 = a0 * inv, v1 = a1 * inv;
        __half h0, l0, h1, l1;
        split2h(v0, h0, l0);
        split2h(v1, h1, l1);
        yh[off + lane]      = h0;  yl[off + lane]      = l0;
        yh[off + lane + 32] = h1;  yl[off + lane + 32] = l1;
    }
}

// ============== mma.sync fp16 2-term GEMM: C = A(MxK) * W(NxK)^T + epilogue ==============
// A exact via hi/lo fp16 split (2 planes); W rounded to fp16 (1 plane).
// 128x128 CTA tile, 8 warps (4m x 2n), warp tile 32x64, chunk K=32, cp.async double buffer.
// Packed 64B rows + XOR swizzle: chunk' = chunk ^ ((row>>1)&3). 2 CTAs/SM.
#define PLANE_BYTES 8192                  // 128 rows x 64B
#define BUF_BYTES (3*PLANE_BYTES)         // 24576
#define GEMM_SMEM (2*BUF_BYTES)           // 49152

#define SWZ_ADDR(base, row, chunk) \
    ((base) + (uint32_t)(row)*64u + (uint32_t)(((chunk) ^ (((row)>>1)&3)) << 4))

template<int EPI>
__global__ __launch_bounds__(256, 2)
void gemm_mma(const __half* __restrict__ Ah, const __half* __restrict__ Al,
              const __half* __restrict__ Bh,
              const float* __restrict__ bias, const float* __restrict__ res,
              float* __restrict__ Cf, __half* __restrict__ Chi,
              __half* __restrict__ Clo, int N, int K) {
    extern __shared__ char gsm[];
    uint32_t sb = smem_to_u32(gsm);
    int tid = threadIdx.x, lane = tid & 31, wid = tid >> 5;
    int rowBase = blockIdx.y * 128, colBase = blockIdx.x * 128;

    int wm = wid & 3, wn = wid >> 2;      // 4x2 warp grid
    int m0 = wm * 32, n0 = wn * 64;

    float acc[2][8][4];
    #pragma unroll
    for (int i = 0; i < 2; i++)
        #pragma unroll
        for (int j = 0; j < 8; j++)
            #pragma unroll
            for (int q = 0; q < 4; q++) acc[i][j][q] = 0.f;

    // per-lane ldmatrix row/chunk components
    int arow_l = (lane & 15);
    int acb    = (lane >> 4);
    int brow_l = (lane & 7) + ((lane >> 4) << 3);
    int bcb    = (lane >> 3) & 1;

    // loader: 3 planes x 128 rows x 64B, 6 x 16B transfers per thread
    auto load_chunk = [&](int buf, int k0) {
        uint32_t sbase = sb + buf * BUF_BYTES;
        int row = tid >> 1, c0 = (tid & 1) * 2;
        uint32_t so  = SWZ_ADDR(sbase, row, c0);
        uint32_t so1 = SWZ_ADDR(sbase, row, c0 + 1);
        size_t goA = (size_t)(rowBase + row) * K + k0 + c0 * 8;
        size_t goB = (size_t)(colBase + row) * K + k0 + c0 * 8;
        cp_async16(so,                     Ah + goA);
        cp_async16(so1,                    Ah + goA + 8);
        cp_async16(PLANE_BYTES   + so,     Al + goA);
        cp_async16(PLANE_BYTES   + so1,    Al + goA + 8);
        cp_async16(2*PLANE_BYTES + so,     Bh + goB);
        cp_async16(2*PLANE_BYTES + so1,    Bh + goB + 8);
    };

    int NC = K >> 5;
    load_chunk(0, 0);
    CP_COMMIT();

    for (int c = 0; c < NC; c++) {
        int buf = c & 1;
        if (c + 1 < NC) {
            load_chunk(buf ^ 1, (c + 1) << 5);
            CP_COMMIT();
            CP_WAIT1();
        } else {
            CP_WAIT0();
        }
        __syncthreads();

        uint32_t pA = sb + buf * BUF_BYTES;
        #pragma unroll
        for (int ks = 0; ks < 2; ks++) {
            uint32_t ah[2][4], al[2][4];
            #pragma unroll
            for (int mt = 0; mt < 2; mt++) {
                int ar = m0 + mt * 16 + arow_l;
                uint32_t ad = SWZ_ADDR(pA, ar, ks * 2 + acb);
                ldsm_x4(ah[mt][0], ah[mt][1], ah[mt][2], ah[mt][3], ad);
                ldsm_x4(al[mt][0], al[mt][1], al[mt][2], al[mt][3], ad + PLANE_BYTES);
            }
            #pragma unroll
            for (int ng = 0; ng < 4; ng++) {
                int br = n0 + ng * 16 + brow_l;
                uint32_t bd = SWZ_ADDR(pA + 2*PLANE_BYTES, br, ks * 2 + bcb);
                uint32_t bh2[2][2];
                ldsm_x4(bh2[0][0], bh2[0][1], bh2[1][0], bh2[1][1], bd);
                #pragma unroll
                for (int mt = 0; mt < 2; mt++)
                    #pragma unroll
                    for (int j = 0; j < 2; j++) {
                        int nt = 2*ng + j;
                        mma_f16(acc[mt][nt], ah[mt], bh2[j]);
                        mma_f16(acc[mt][nt], al[mt], bh2[j]);
                    }
            }
        }
        __syncthreads();
    }

    // ---- epilogue ----
    int rbase = rowBase + m0 + (lane >> 2);
    int cbase = colBase + n0 + (lane & 3) * 2;
    #pragma unroll
    for (int mt = 0; mt < 2; mt++) {
        #pragma unroll
        for (int half = 0; half < 2; half++) {
            int row = rbase + mt * 16 + half * 8;
            if (EPI == 0) {
                float* crow = Cf + (size_t)row * N;
                const float* rrow = res + (size_t)row * N;
                #pragma unroll
                for (int nt = 0; nt < 8; nt++) {
                    int col = cbase + nt * 8;
                    float2 o;
                    o.x = acc[mt][nt][half*2+0] + bias[col]   + rrow[col];
                    o.y = acc[mt][nt][half*2+1] + bias[col+1] + rrow[col+1];
                    *(float2*)(crow + col) = o;
                }
            } else {
                __half* hrow = Chi + (size_t)row * N;
                __half* lrow = Clo + (size_t)row * N;
                #pragma unroll
                for (int nt = 0; nt < 8; nt++) {
                    int col = cbase + nt * 8;
                    float v0 = acc[mt][nt][half*2+0] + bias[col];
                    float v1 = acc[mt][nt][half*2+1] + bias[col+1];
                    v0 = 0.5f * v0 * (1.0f + erff(v0 * 0.70710678118654752f));
                    v1 = 0.5f * v1 * (1.0f + erff(v1 * 0.70710678118654752f));
                    __half h0, l0, h1, l1;
                    split2h(v0, h0, l0);
                    split2h(v1, h1, l1);
                    __half hh[2] = {h0, h1}, ll[2] = {l0, l1};
                    *(uint32_t*)(hrow + col) = *(uint32_t*)hh;
                    *(uint32_t*)(lrow + col) = *(uint32_t*)ll;
                }
            }
        }
    }
}

// ---------------- launch ----------------
extern "C" void kernel_launch(void* const* d_in, const int* in_sizes, int n_in,
                              void* d_out, int out_size) {
    const float* x      = (const float*)d_in[0];
    const float* wrf    = (const float*)d_in[1];
    const float* kqv_w  = (const float*)d_in[2];
    const float* kqv_b  = (const float*)d_in[3];
    const float* proj_w = (const float*)d_in[4];
    const float* proj_b = (const float*)d_in[5];
    const float* ln1_g  = (const float*)d_in[6];
    const float* ln1_b  = (const float*)d_in[7];
    const float* ln2_g  = (const float*)d_in[8];
    const float* ln2_b  = (const float*)d_in[9];
    const float* mlp_w1 = (const float*)d_in[10];
    const float* mlp_b1 = (const float*)d_in[11];
    const float* mlp_w2 = (const float*)d_in[12];
    const float* mlp_b2 = (const float*)d_in[13];
    float* out = (float*)d_out;

    float *p_h2, *p_v, *p_qp, *p_kp, *p_pk, *p_ps, *p_kptv, *p_ksum, *p_x1;
    __half *p_h2h, *p_h2l, *p_yh, *p_yl, *p_hidh, *p_hidl;
    __half *p_pwh, *p_w1h, *p_w2h;
    cudaGetSymbolAddress((void**)&p_h2,   g_h2);
    cudaGetSymbolAddress((void**)&p_v,    g_v);
    cudaGetSymbolAddress((void**)&p_qp,   g_qp);
    cudaGetSymbolAddress((void**)&p_kp,   g_kp);
    cudaGetSymbolAddress((void**)&p_pk,   g_kptv_part);
    cudaGetSymbolAddress((void**)&p_ps,   g_ksum_part);
    cudaGetSymbolAddress((void**)&p_kptv, g_kptv);
    cudaGetSymbolAddress((void**)&p_ksum, g_ksum);
    cudaGetSymbolAddress((void**)&p_x1,   g_x1);
    cudaGetSymbolAddress((void**)&p_h2h,  g_h2h);
    cudaGetSymbolAddress((void**)&p_h2l,  g_h2l);
    cudaGetSymbolAddress((void**)&p_yh,   g_yh);
    cudaGetSymbolAddress((void**)&p_yl,   g_yl);
    cudaGetSymbolAddress((void**)&p_hidh, g_hidh);
    cudaGetSymbolAddress((void**)&p_hidl, g_hidl);
    cudaGetSymbolAddress((void**)&p_pwh,  g_pwh);
    cudaGetSymbolAddress((void**)&p_w1h,  g_w1h);
    cudaGetSymbolAddress((void**)&p_w2h,  g_w2h);

    const size_t k1_smem = (size_t)K1_SMEM_FLOATS * sizeof(float);
    cudaFuncSetAttribute(kqv_prm_kernel, cudaFuncAttributeMaxDynamicSharedMemorySize,
                         (int)k1_smem);
    cudaFuncSetAttribute(gemm_mma<0>, cudaFuncAttributeMaxDynamicSharedMemorySize, GEMM_SMEM);
    cudaFuncSetAttribute(gemm_mma<1>, cudaFuncAttributeMaxDynamicSharedMemorySize, GEMM_SMEM);

    // 0. weight fp16 rounds
    cvt_h_kernel<<<(EMB*EMB/4 + 255)/256, 256>>>(proj_w, p_pwh, EMB*EMB/4);
    cvt_h_kernel<<<(HID*EMB/4 + 255)/256, 256>>>(mlp_w1, p_w1h, HID*EMB/4);
    cvt_h_kernel<<<(EMB*HID/4 + 255)/256, 256>>>(mlp_w2, p_w2h, EMB*HID/4);
    // 1. LN1
    ln_kernel<0><<<NTOK/8, 256>>>(x, ln1_g, ln1_b, p_h2, nullptr, nullptr);
    // 2. kqv + prm_exp
    kqv_prm_kernel<<<NTOK/8, 256, k1_smem>>>(p_h2, kqv_w, kqv_b, wrf, p_v, p_kp, p_qp);
    // 3-4. kptv/ksum reduction over T
    kpt_kernel<<<dim3(16, 64), 256>>>(p_v, p_kp, p_pk, p_ps);
    reduce_kernel<<<513, 256>>>(p_pk, p_ps, p_kptv, p_ksum);
    // 5. y (fp16 hi/lo planes)
    y_kernel<<<dim3(TQ/256, 64), 256>>>(p_qp, p_kptv, p_ksum, p_yh, p_yl);
    // 6. attn proj + residual -> x1 (fp32)
    gemm_mma<0><<<dim3(EMB/128, NTOK/128), 256, GEMM_SMEM>>>(
        p_yh, p_yl, p_pwh, proj_b, x, p_x1, nullptr, nullptr, EMB, EMB);
    // 7. LN2 -> fp16 hi/lo planes
    ln_kernel<1><<<NTOK/8, 256>>>(p_x1, ln2_g, ln2_b, nullptr, p_h2h, p_h2l);
    // 8. mlp1 + gelu -> hid fp16 hi/lo planes
    gemm_mma<1><<<dim3(HID/128, NTOK/128), 256, GEMM_SMEM>>>(
        p_h2h, p_h2l, p_w1h, mlp_b1, nullptr, nullptr, p_hidh, p_hidl, HID, EMB);
    // 9. mlp2 + residual -> out (fp32)
    gemm_mma<0><<<dim3(EMB/128, NTOK/128), 256, GEMM_SMEM>>>(
        p_hidh, p_hidl, p_w2h, mlp_b2, p_x1, out, nullptr, nullptr, EMB, HID);
}

// round 7
// speedup vs baseline: 3.2399x; 1.2659x over previous
#include <cuda_runtime.h>
#include <cuda_fp16.h>
#include <math.h>
#include <stdint.h>

// Problem constants
#define BQ 8
#define TQ 4096
#define NTOK (BQ*TQ)          // 32768 tokens
#define EMB 512
#define HEADS 8
#define ES 64
#define MF 32                 // random features
#define HID (4*EMB)           // 2048
#define LN_EPS 1e-5f

__device__ __forceinline__ uint32_t smem_to_u32(const void* smem_ptr) {
    uint32_t addr;
    asm("{ .reg .u64 tmp; cvta.to.shared.u64 tmp, %1; cvt.u32.u64 %0, tmp; }"
        : "=r"(addr) : "l"(smem_ptr));
    return addr;
}

__device__ __forceinline__ void cp_async16(uint32_t saddr, const void* gaddr) {
    asm volatile("cp.async.cg.shared.global [%0], [%1], 16;" :: "r"(saddr), "l"(gaddr));
}
#define CP_COMMIT() asm volatile("cp.async.commit_group;" ::: "memory")
#define CP_WAIT0()  asm volatile("cp.async.wait_group 0;" ::: "memory")
#define CP_WAIT1()  asm volatile("cp.async.wait_group 1;" ::: "memory")

__device__ __forceinline__ void ldsm_x4(uint32_t& r0, uint32_t& r1, uint32_t& r2, uint32_t& r3,
                                        uint32_t addr) {
    asm volatile("ldmatrix.sync.aligned.m8n8.x4.shared.b16 {%0,%1,%2,%3}, [%4];"
        : "=r"(r0), "=r"(r1), "=r"(r2), "=r"(r3) : "r"(addr));
}

__device__ __forceinline__ void mma_f16(float* c, const uint32_t* a, const uint32_t* b) {
    asm volatile(
        "mma.sync.aligned.m16n8k16.row.col.f32.f16.f16.f32 "
        "{%0,%1,%2,%3}, {%4,%5,%6,%7}, {%8,%9}, {%0,%1,%2,%3};"
        : "+f"(c[0]), "+f"(c[1]), "+f"(c[2]), "+f"(c[3])
        : "r"(a[0]), "r"(a[1]), "r"(a[2]), "r"(a[3]), "r"(b[0]), "r"(b[1]));
}

// -------- scratch (device globals; no runtime allocation) --------
__device__ float g_h2[(size_t)NTOK*EMB];
__device__ float g_v[(size_t)NTOK*HEADS*ES];
__device__ float g_qp[(size_t)NTOK*HEADS*MF];
__device__ float g_kp[(size_t)NTOK*HEADS*MF];
__device__ float g_kptv_part[16*64*ES*MF];
__device__ float g_ksum_part[16*64*MF];
__device__ float g_kptv[64*ES*MF];
__device__ float g_ksum[64*MF];
__device__ float g_x1[(size_t)NTOK*EMB];
// fp16 activations + weights (single plane each)
__device__ __align__(16) __half g_h2h[(size_t)NTOK*EMB];
__device__ __align__(16) __half g_yh[(size_t)NTOK*EMB];
__device__ __align__(16) __half g_hidh[(size_t)NTOK*HID];
__device__ __align__(16) __half g_pwh[EMB*EMB];
__device__ __align__(16) __half g_w1h[HID*EMB];
__device__ __align__(16) __half g_w2h[EMB*HID];

// ---------------- weight fp16 conversion ----------------
__global__ void cvt_h_kernel(const float* __restrict__ w, __half* __restrict__ hi, int n4) {
    int i = blockIdx.x * 256 + threadIdx.x;
    if (i < n4) {
        float4 v = ((const float4*)w)[i];
        __half h[4];
        h[0] = __float2half(v.x); h[1] = __float2half(v.y);
        h[2] = __float2half(v.z); h[3] = __float2half(v.w);
        *(uint2*)(hi + (size_t)i*4) = *(uint2*)h;
    }
}

// ---------------- LayerNorm: warp per token ----------------
// MODE 0: fp32 out.  MODE 1: fp16 out.
template<int MODE>
__global__ void ln_kernel(const float* __restrict__ x, const float* __restrict__ g,
                          const float* __restrict__ b, float* __restrict__ out,
                          __half* __restrict__ ohi) {
    int tok  = blockIdx.x * 8 + (threadIdx.x >> 5);
    int lane = threadIdx.x & 31;
    const float4* xr = (const float4*)(x + (size_t)tok * EMB);
    float4 v[4];
    float s = 0.f, sq = 0.f;
    #pragma unroll
    for (int i = 0; i < 4; i++) {
        v[i] = xr[lane + 32*i];
        s  += v[i].x + v[i].y + v[i].z + v[i].w;
        sq += v[i].x*v[i].x + v[i].y*v[i].y + v[i].z*v[i].z + v[i].w*v[i].w;
    }
    #pragma unroll
    for (int o = 16; o; o >>= 1) {
        s  += __shfl_xor_sync(0xffffffffu, s,  o);
        sq += __shfl_xor_sync(0xffffffffu, sq, o);
    }
    float mean = s * (1.0f/EMB);
    float var  = sq * (1.0f/EMB) - mean*mean;
    float rstd = rsqrtf(var + LN_EPS);
    const float4* g4 = (const float4*)g;
    const float4* b4 = (const float4*)b;
    #pragma unroll
    for (int i = 0; i < 4; i++) {
        float4 gg = g4[lane + 32*i], bb = b4[lane + 32*i];
        float4 o;
        o.x = (v[i].x - mean) * rstd * gg.x + bb.x;
        o.y = (v[i].y - mean) * rstd * gg.y + bb.y;
        o.z = (v[i].z - mean) * rstd * gg.z + bb.z;
        o.w = (v[i].w - mean) * rstd * gg.w + bb.w;
        if (MODE == 0) {
            ((float4*)(out + (size_t)tok * EMB))[lane + 32*i] = o;
        } else {
            size_t idx = (size_t)tok * EMB + (size_t)(lane + 32*i) * 4;
            __half h[4];
            h[0] = __float2half(o.x); h[1] = __float2half(o.y);
            h[2] = __float2half(o.z); h[3] = __float2half(o.w);
            *(uint2*)(ohi + idx) = *(uint2*)h;
        }
    }
}

// ---------------- kqv + prm_exp (8 tokens per block) ----------------
#define K1_SMEM_FLOATS (4096 + 12288 + 2048 + 192 + 1536 + 16)
__global__ void kqv_prm_kernel(const float* __restrict__ hN, const float* __restrict__ kqv_w,
                               const float* __restrict__ kqv_b, const float* __restrict__ wrf,
                               float* __restrict__ gv, float* __restrict__ gkp,
                               float* __restrict__ gqp) {
    extern __shared__ float sm[];
    float* sh_h  = sm;
    float* wk_t  = sm + 4096;
    float* wr_t  = wk_t + 12288;
    float* sbias = wr_t + 2048;
    float* skqv  = sbias + 192;
    float* sxd   = skqv + 1536;
    int tid = threadIdx.x;
    size_t t0 = (size_t)blockIdx.x * 8;

    {
        const float4* src = (const float4*)(hN + t0 * EMB);
        float4* dst = (float4*)sh_h;
        #pragma unroll
        for (int i = 0; i < 4; i++) dst[tid + 256*i] = src[tid + 256*i];
    }
    #pragma unroll
    for (int i = 0; i < 12; i++) {
        int j = tid + 256*i;
        int f = j >> 4, e0 = (j & 15) << 2;
        float4 w4 = ((const float4*)kqv_w)[j];
        wk_t[(e0+0)*192 + f] = w4.x;
        wk_t[(e0+1)*192 + f] = w4.y;
        wk_t[(e0+2)*192 + f] = w4.z;
        wk_t[(e0+3)*192 + f] = w4.w;
    }
    #pragma unroll
    for (int i = 0; i < 2; i++) {
        int j = tid + 256*i;
        int m = j >> 4, e0 = (j & 15) << 2;
        float4 w4 = ((const float4*)wrf)[j];
        wr_t[(e0+0)*32 + m] = w4.x;
        wr_t[(e0+1)*32 + m] = w4.y;
        wr_t[(e0+2)*32 + m] = w4.z;
        wr_t[(e0+3)*32 + m] = w4.w;
    }
    if (tid < 192) sbias[tid] = kqv_b[tid];
    __syncthreads();

    int fg = tid & 63, tg = tid >> 6;
    int f0 = fg * 3, tokA = tg * 2;

    for (int hd = 0; hd < HEADS; hd++) {
        float a00=0,a01=0,a10=0,a11=0,a20=0,a21=0;
        const float* hb = sh_h + hd * 64;
        #pragma unroll 8
        for (int e = 0; e < 64; e++) {
            float w0 = wk_t[e*192 + f0];
            float w1 = wk_t[e*192 + f0 + 1];
            float w2 = wk_t[e*192 + f0 + 2];
            float h0 = hb[tokA*512 + e];
            float h1 = hb[(tokA+1)*512 + e];
            a00 += w0*h0; a01 += w0*h1;
            a10 += w1*h0; a11 += w1*h1;
            a20 += w2*h0; a21 += w2*h1;
        }
        skqv[tokA*192 + f0 + 0] = a00 + sbias[f0+0];
        skqv[tokA*192 + f0 + 1] = a10 + sbias[f0+1];
        skqv[tokA*192 + f0 + 2] = a20 + sbias[f0+2];
        skqv[(tokA+1)*192 + f0 + 0] = a01 + sbias[f0+0];
        skqv[(tokA+1)*192 + f0 + 1] = a11 + sbias[f0+1];
        skqv[(tokA+1)*192 + f0 + 2] = a21 + sbias[f0+2];
        __syncthreads();

        #pragma unroll
        for (int i = 0; i < 2; i++) {
            int idx = tid + 256*i;
            int tok = idx >> 6, e = idx & 63;
            gv[(((t0 + tok) * HEADS) + hd) * ES + e] = skqv[tok*192 + 128 + e];
        }
        if (tid < 16) {
            int tok = tid >> 1, which = tid & 1;
            const float* z = skqv + tok*192 + which*64;
            float s = 0.f;
            #pragma unroll 8
            for (int e = 0; e < 64; e++) { float zz = z[e]; s += zz*zz; }
            sxd[tid] = 0.5f * s;
        }
        __syncthreads();

        #pragma unroll
        for (int i = 0; i < 2; i++) {
            int idx = tid + 256*i;
            int m = idx & 31, which = (idx >> 5) & 1, tok = idx >> 6;
            const float* z = skqv + tok*192 + which*64;
            float a = 0.f;
            #pragma unroll 8
            for (int e = 0; e < 64; e++) a += z[e] * wr_t[e*32 + m];
            float val = expf(a - sxd[tok*2 + which]) * 0.17677669529663689f;
            float* dst = which ? gqp : gkp;
            dst[(((t0 + tok) * HEADS) + hd) * MF + m] = val;
        }
        __syncthreads();
    }
}

// ---------------- kptv / ksum partial reduction over T ----------------
__global__ void kpt_kernel(const float* __restrict__ gv, const float* __restrict__ gkp,
                           float* __restrict__ part_kptv, float* __restrict__ part_ksum) {
    int chunk = blockIdx.x;
    int bh = blockIdx.y;
    int b = bh >> 3, h = bh & 7;
    __shared__ float sv[16][64];
    __shared__ float skp[16][32];
    int tid = threadIdx.x, lane = tid & 31, wid = tid >> 5;
    float acc[8] = {0,0,0,0,0,0,0,0};
    float ks = 0.f;
    int t0 = chunk * 256;
    for (int st = 0; st < 16; st++) {
        int s0 = t0 + st * 16;
        __syncthreads();
        #pragma unroll
        for (int i = 0; i < 4; i++) {
            int idx = tid + 256*i;
            int s = idx >> 6, e = idx & 63;
            sv[s][e] = gv[((((size_t)b*TQ + s0 + s) * HEADS) + h) * ES + e];
        }
        #pragma unroll
        for (int i = 0; i < 2; i++) {
            int idx = tid + 256*i;
            int s = idx >> 5, m = idx & 31;
            skp[s][m] = gkp[((((size_t)b*TQ + s0 + s) * HEADS) + h) * MF + m];
        }
        __syncthreads();
        #pragma unroll
        for (int s = 0; s < 16; s++) {
            float kv = skp[s][lane];
            float4 va = *(const float4*)&sv[s][wid*8];
            float4 vb = *(const float4*)&sv[s][wid*8 + 4];
            acc[0] += va.x*kv; acc[1] += va.y*kv; acc[2] += va.z*kv; acc[3] += va.w*kv;
            acc[4] += vb.x*kv; acc[5] += vb.y*kv; acc[6] += vb.z*kv; acc[7] += vb.w*kv;
            if (wid == 0) ks += kv;
        }
    }
    size_t base = ((size_t)(chunk*64 + bh)) * (ES*MF);
    #pragma unroll
    for (int j = 0; j < 8; j++)
        part_kptv[base + (wid*8 + j)*MF + lane] = acc[j];
    if (wid == 0) part_ksum[(chunk*64 + bh)*MF + lane] = ks;
}

__global__ void reduce_kernel(const float* __restrict__ pk, const float* __restrict__ ps,
                              float* __restrict__ kptv, float* __restrict__ ksum) {
    int bid = blockIdx.x;
    if (bid < 512) {
        int idx = bid * 256 + threadIdx.x;
        int bh = idx >> 11;
        float s = 0.f;
        #pragma unroll
        for (int c = 0; c < 16; c++) s += pk[((size_t)(c*64 + bh)) * 2048 + (idx & 2047)];
        kptv[idx] = s;
    } else {
        #pragma unroll
        for (int j = 0; j < 8; j++) {
            int idx = threadIdx.x * 8 + j;
            int bh = idx >> 5, m = idx & 31;
            float s = 0.f;
            #pragma unroll
            for (int c = 0; c < 16; c++) s += ps[(c*64 + bh)*MF + m];
            ksum[idx] = s;
        }
    }
}

// ---------------- y = (qp . kptv) / D  -> fp16 ----------------
__global__ void y_kernel(const float* __restrict__ gqp, const float* __restrict__ kptv,
                         const float* __restrict__ ksum, __half* __restrict__ yh) {
    int bh = blockIdx.y, b = bh >> 3, h = bh & 7;
    __shared__ float sk[64*33];
    __shared__ float sks[32];
    int tid = threadIdx.x, lane = tid & 31, wid = tid >> 5;
    #pragma unroll
    for (int i = 0; i < 8; i++) {
        int idx = tid + 256*i;
        sk[(idx >> 5)*33 + (idx & 31)] = kptv[(size_t)bh*2048 + idx];
    }
    if (tid < 32) sks[tid] = ksum[bh*32 + tid];
    __syncthreads();
    float ksv = sks[lane];
    for (int it = 0; it < 32; it++) {
        int t = blockIdx.x * 256 + wid * 32 + it;
        float qpv = gqp[((((size_t)b*TQ + t) * HEADS) + h) * MF + lane];
        float d = qpv * ksv;
        #pragma unroll
        for (int o = 16; o; o >>= 1) d += __shfl_xor_sync(0xffffffffu, d, o);
        float a0 = 0.f, a1 = 0.f;
        #pragma unroll
        for (int m = 0; m < 32; m++) {
            float qm = __shfl_sync(0xffffffffu, qpv, m);
            a0 += qm * sk[lane*33 + m];
            a1 += qm * sk[(lane+32)*33 + m];
        }
        float inv = 1.0f / d;
        size_t off = ((size_t)b*TQ + t) * EMB + h * ES;
        yh[off + lane]      = __float2half(a0 * inv);
        yh[off + lane + 32] = __float2half(a1 * inv);
    }
}

// ============== mma.sync fp16 GEMM (fp32 accum): C = A(MxK) * W(NxK)^T + epilogue ==============
// 128x128 CTA tile, 8 warps (4m x 2n), warp tile 32x64, chunk K=64, cp.async double buffer.
// 128B rows, canonical SW128 swizzle: chunk' = chunk ^ (row&7). 2 CTAs/SM.
#define PLANE_BYTES 16384                 // 128 rows x 128B
#define BUF_BYTES (2*PLANE_BYTES)         // 32768
#define GEMM_SMEM (2*BUF_BYTES)           // 65536

#define SWZ_ADDR(base, row, chunk) \
    ((base) + (uint32_t)(row)*128u + (uint32_t)(((chunk) ^ ((row)&7)) << 4))

template<int EPI>
__global__ __launch_bounds__(256, 2)
void gemm_mma(const __half* __restrict__ Ah, const __half* __restrict__ Bh,
              const float* __restrict__ bias, const float* __restrict__ res,
              float* __restrict__ Cf, __half* __restrict__ Chi, int N, int K) {
    extern __shared__ char gsm[];
    uint32_t sb = smem_to_u32(gsm);
    int tid = threadIdx.x, lane = tid & 31, wid = tid >> 5;
    int rowBase = blockIdx.y * 128, colBase = blockIdx.x * 128;

    int wm = wid & 3, wn = wid >> 2;      // 4x2 warp grid
    int m0 = wm * 32, n0 = wn * 64;

    float acc[2][8][4];
    #pragma unroll
    for (int i = 0; i < 2; i++)
        #pragma unroll
        for (int j = 0; j < 8; j++)
            #pragma unroll
            for (int q = 0; q < 4; q++) acc[i][j][q] = 0.f;

    // per-lane ldmatrix row/chunk components
    int arow_l = (lane & 15);
    int acb    = (lane >> 4);
    int brow_l = (lane & 7) + ((lane >> 4) << 3);
    int bcb    = (lane >> 3) & 1;

    // loader: 2 planes x 128 rows x 128B, 8 x 16B transfers per thread
    auto load_chunk = [&](int buf, int k0) {
        uint32_t sbase = sb + buf * BUF_BYTES;
        int row = tid >> 1, c0 = (tid & 1) * 4;
        size_t goA = (size_t)(rowBase + row) * K + k0 + c0 * 8;
        size_t goB = (size_t)(colBase + row) * K + k0 + c0 * 8;
        #pragma unroll
        for (int j = 0; j < 4; j++) {
            uint32_t so = SWZ_ADDR(sbase, row, c0 + j);
            cp_async16(so,               Ah + goA + j * 8);
            cp_async16(PLANE_BYTES + so, Bh + goB + j * 8);
        }
    };

    int NC = K >> 6;
    load_chunk(0, 0);
    CP_COMMIT();

    for (int c = 0; c < NC; c++) {
        int buf = c & 1;
        if (c + 1 < NC) {
            load_chunk(buf ^ 1, (c + 1) << 6);
            CP_COMMIT();
            CP_WAIT1();
        } else {
            CP_WAIT0();
        }
        __syncthreads();

        uint32_t pA = sb + buf * BUF_BYTES;
        #pragma unroll
        for (int ks = 0; ks < 4; ks++) {
            uint32_t ah[2][4];
            #pragma unroll
            for (int mt = 0; mt < 2; mt++) {
                int ar = m0 + mt * 16 + arow_l;
                uint32_t ad = SWZ_ADDR(pA, ar, ks * 2 + acb);
                ldsm_x4(ah[mt][0], ah[mt][1], ah[mt][2], ah[mt][3], ad);
            }
            #pragma unroll
            for (int ng = 0; ng < 4; ng++) {
                int br = n0 + ng * 16 + brow_l;
                uint32_t bd = SWZ_ADDR(pA + PLANE_BYTES, br, ks * 2 + bcb);
                uint32_t bh2[2][2];
                ldsm_x4(bh2[0][0], bh2[0][1], bh2[1][0], bh2[1][1], bd);
                #pragma unroll
                for (int mt = 0; mt < 2; mt++)
                    #pragma unroll
                    for (int j = 0; j < 2; j++)
                        mma_f16(acc[mt][2*ng + j], ah[mt], bh2[j]);
            }
        }
        __syncthreads();
    }

    // ---- epilogue ----
    int rbase = rowBase + m0 + (lane >> 2);
    int cbase = colBase + n0 + (lane & 3) * 2;
    #pragma unroll
    for (int mt = 0; mt < 2; mt++) {
        #pragma unroll
        for (int half = 0; half < 2; half++) {
            int row = rbase + mt * 16 + half * 8;
            if (EPI == 0) {
                float* crow = Cf + (size_t)row * N;
                const float* rrow = res + (size_t)row * N;
                #pragma unroll
                for (int nt = 0; nt < 8; nt++) {
                    int col = cbase + nt * 8;
                    float2 o;
                    o.x = acc[mt][nt][half*2+0] + bias[col]   + rrow[col];
                    o.y = acc[mt][nt][half*2+1] + bias[col+1] + rrow[col+1];
                    *(float2*)(crow + col) = o;
                }
            } else {
                __half* hrow = Chi + (size_t)row * N;
                #pragma unroll
                for (int nt = 0; nt < 8; nt++) {
                    int col = cbase + nt * 8;
                    float v0 = acc[mt][nt][half*2+0] + bias[col];
                    float v1 = acc[mt][nt][half*2+1] + bias[col+1];
                    v0 = 0.5f * v0 * (1.0f + erff(v0 * 0.70710678118654752f));
                    v1 = 0.5f * v1 * (1.0f + erff(v1 * 0.70710678118654752f));
                    __half hh[2] = {__float2half(v0), __float2half(v1)};
                    *(uint32_t*)(hrow + col) = *(uint32_t*)hh;
                }
            }
        }
    }
}

// ---------------- launch ----------------
extern "C" void kernel_launch(void* const* d_in, const int* in_sizes, int n_in,
                              void* d_out, int out_size) {
    const float* x      = (const float*)d_in[0];
    const float* wrf    = (const float*)d_in[1];
    const float* kqv_w  = (const float*)d_in[2];
    const float* kqv_b  = (const float*)d_in[3];
    const float* proj_w = (const float*)d_in[4];
    const float* proj_b = (const float*)d_in[5];
    const float* ln1_g  = (const float*)d_in[6];
    const float* ln1_b  = (const float*)d_in[7];
    const float* ln2_g  = (const float*)d_in[8];
    const float* ln2_b  = (const float*)d_in[9];
    const float* mlp_w1 = (const float*)d_in[10];
    const float* mlp_b1 = (const float*)d_in[11];
    const float* mlp_w2 = (const float*)d_in[12];
    const float* mlp_b2 = (const float*)d_in[13];
    float* out = (float*)d_out;

    float *p_h2, *p_v, *p_qp, *p_kp, *p_pk, *p_ps, *p_kptv, *p_ksum, *p_x1;
    __half *p_h2h, *p_yh, *p_hidh, *p_pwh, *p_w1h, *p_w2h;
    cudaGetSymbolAddress((void**)&p_h2,   g_h2);
    cudaGetSymbolAddress((void**)&p_v,    g_v);
    cudaGetSymbolAddress((void**)&p_qp,   g_qp);
    cudaGetSymbolAddress((void**)&p_kp,   g_kp);
    cudaGetSymbolAddress((void**)&p_pk,   g_kptv_part);
    cudaGetSymbolAddress((void**)&p_ps,   g_ksum_part);
    cudaGetSymbolAddress((void**)&p_kptv, g_kptv);
    cudaGetSymbolAddress((void**)&p_ksum, g_ksum);
    cudaGetSymbolAddress((void**)&p_x1,   g_x1);
    cudaGetSymbolAddress((void**)&p_h2h,  g_h2h);
    cudaGetSymbolAddress((void**)&p_yh,   g_yh);
    cudaGetSymbolAddress((void**)&p_hidh, g_hidh);
    cudaGetSymbolAddress((void**)&p_pwh,  g_pwh);
    cudaGetSymbolAddress((void**)&p_w1h,  g_w1h);
    cudaGetSymbolAddress((void**)&p_w2h,  g_w2h);

    const size_t k1_smem = (size_t)K1_SMEM_FLOATS * sizeof(float);
    cudaFuncSetAttribute(kqv_prm_kernel, cudaFuncAttributeMaxDynamicSharedMemorySize,
                         (int)k1_smem);
    cudaFuncSetAttribute(gemm_mma<0>, cudaFuncAttributeMaxDynamicSharedMemorySize, GEMM_SMEM);
    cudaFuncSetAttribute(gemm_mma<1>, cudaFuncAttributeMaxDynamicSharedMemorySize, GEMM_SMEM);

    // 0. weight fp16 rounds
    cvt_h_kernel<<<(EMB*EMB/4 + 255)/256, 256>>>(proj_w, p_pwh, EMB*EMB/4);
    cvt_h_kernel<<<(HID*EMB/4 + 255)/256, 256>>>(mlp_w1, p_w1h, HID*EMB/4);
    cvt_h_kernel<<<(EMB*HID/4 + 255)/256, 256>>>(mlp_w2, p_w2h, EMB*HID/4);
    // 1. LN1
    ln_kernel<0><<<NTOK/8, 256>>>(x, ln1_g, ln1_b, p_h2, nullptr);
    // 2. kqv + prm_exp
    kqv_prm_kernel<<<NTOK/8, 256, k1_smem>>>(p_h2, kqv_w, kqv_b, wrf, p_v, p_kp, p_qp);
    // 3-4. kptv/ksum reduction over T
    kpt_kernel<<<dim3(16, 64), 256>>>(p_v, p_kp, p_pk, p_ps);
    reduce_kernel<<<513, 256>>>(p_pk, p_ps, p_kptv, p_ksum);
    // 5. y (fp16)
    y_kernel<<<dim3(TQ/256, 64), 256>>>(p_qp, p_kptv, p_ksum, p_yh);
    // 6. attn proj + residual -> x1 (fp32)
    gemm_mma<0><<<dim3(EMB/128, NTOK/128), 256, GEMM_SMEM>>>(
        p_yh, p_pwh, proj_b, x, p_x1, nullptr, EMB, EMB);
    // 7. LN2 -> fp16
    ln_kernel<1><<<NTOK/8, 256>>>(p_x1, ln2_g, ln2_b, nullptr, p_h2h);
    // 8. mlp1 + gelu -> hid (fp16)
    gemm_mma<1><<<dim3(HID/128, NTOK/128), 256, GEMM_SMEM>>>(
        p_h2h, p_w1h, mlp_b1, nullptr, nullptr, p_hidh, HID, EMB);
    // 9. mlp2 + residual -> out (fp32)
    gemm_mma<0><<<dim3(EMB/128, NTOK/128), 256, GEMM_SMEM>>>(
        p_hidh, p_w2h, mlp_b2, p_x1, out, nullptr, EMB, HID);
}

// round 8
// speedup vs baseline: 3.5782x; 1.1044x over previous
#include <cuda_runtime.h>
#include <cuda_fp16.h>
#include <math.h>
#include <stdint.h>

// Problem constants
#define BQ 8
#define TQ 4096
#define NTOK (BQ*TQ)          // 32768 tokens
#define EMB 512
#define HEADS 8
#define ES 64
#define MF 32                 // random features
#define HID (4*EMB)           // 2048
#define LN_EPS 1e-5f

__device__ __forceinline__ uint32_t smem_to_u32(const void* smem_ptr) {
    uint32_t addr;
    asm("{ .reg .u64 tmp; cvta.to.shared.u64 tmp, %1; cvt.u32.u64 %0, tmp; }"
        : "=r"(addr) : "l"(smem_ptr));
    return addr;
}

__device__ __forceinline__ void cp_async16(uint32_t saddr, const void* gaddr) {
    asm volatile("cp.async.cg.shared.global [%0], [%1], 16;" :: "r"(saddr), "l"(gaddr));
}
#define CP_COMMIT() asm volatile("cp.async.commit_group;" ::: "memory")
#define CP_WAIT0()  asm volatile("cp.async.wait_group 0;" ::: "memory")
#define CP_WAIT1()  asm volatile("cp.async.wait_group 1;" ::: "memory")
#define CP_WAIT2()  asm volatile("cp.async.wait_group 2;" ::: "memory")

__device__ __forceinline__ void ldsm_x4(uint32_t& r0, uint32_t& r1, uint32_t& r2, uint32_t& r3,
                                        uint32_t addr) {
    asm volatile("ldmatrix.sync.aligned.m8n8.x4.shared.b16 {%0,%1,%2,%3}, [%4];"
        : "=r"(r0), "=r"(r1), "=r"(r2), "=r"(r3) : "r"(addr));
}

__device__ __forceinline__ void mma_f16(float* c, const uint32_t* a, const uint32_t* b) {
    asm volatile(
        "mma.sync.aligned.m16n8k16.row.col.f32.f16.f16.f32 "
        "{%0,%1,%2,%3}, {%4,%5,%6,%7}, {%8,%9}, {%0,%1,%2,%3};"
        : "+f"(c[0]), "+f"(c[1]), "+f"(c[2]), "+f"(c[3])
        : "r"(a[0]), "r"(a[1]), "r"(a[2]), "r"(a[3]), "r"(b[0]), "r"(b[1]));
}

// -------- scratch (device globals; no runtime allocation) --------
__device__ float g_h2[(size_t)NTOK*EMB];
__device__ float g_v[(size_t)NTOK*HEADS*ES];
__device__ float g_qp[(size_t)NTOK*HEADS*MF];
__device__ float g_kp[(size_t)NTOK*HEADS*MF];
__device__ float g_kptv_part[16*64*ES*MF];
__device__ float g_ksum_part[16*64*MF];
__device__ float g_kptv[64*ES*MF];
__device__ float g_ksum[64*MF];
__device__ float g_x1[(size_t)NTOK*EMB];
// fp16 activations + weights (single plane each)
__device__ __align__(16) __half g_h2h[(size_t)NTOK*EMB];
__device__ __align__(16) __half g_yh[(size_t)NTOK*EMB];
__device__ __align__(16) __half g_hidh[(size_t)NTOK*HID];
__device__ __align__(16) __half g_pwh[EMB*EMB];
__device__ __align__(16) __half g_w1h[HID*EMB];
__device__ __align__(16) __half g_w2h[EMB*HID];

// ---------------- weight fp16 conversion ----------------
__global__ void cvt_h_kernel(const float* __restrict__ w, __half* __restrict__ hi, int n4) {
    int i = blockIdx.x * 256 + threadIdx.x;
    if (i < n4) {
        float4 v = ((const float4*)w)[i];
        __half h[4];
        h[0] = __float2half(v.x); h[1] = __float2half(v.y);
        h[2] = __float2half(v.z); h[3] = __float2half(v.w);
        *(uint2*)(hi + (size_t)i*4) = *(uint2*)h;
    }
}

// ---------------- LayerNorm: warp per token ----------------
// MODE 0: fp32 out.  MODE 1: fp16 out.
template<int MODE>
__global__ void ln_kernel(const float* __restrict__ x, const float* __restrict__ g,
                          const float* __restrict__ b, float* __restrict__ out,
                          __half* __restrict__ ohi) {
    int tok  = blockIdx.x * 8 + (threadIdx.x >> 5);
    int lane = threadIdx.x & 31;
    const float4* xr = (const float4*)(x + (size_t)tok * EMB);
    float4 v[4];
    float s = 0.f, sq = 0.f;
    #pragma unroll
    for (int i = 0; i < 4; i++) {
        v[i] = xr[lane + 32*i];
        s  += v[i].x + v[i].y + v[i].z + v[i].w;
        sq += v[i].x*v[i].x + v[i].y*v[i].y + v[i].z*v[i].z + v[i].w*v[i].w;
    }
    #pragma unroll
    for (int o = 16; o; o >>= 1) {
        s  += __shfl_xor_sync(0xffffffffu, s,  o);
        sq += __shfl_xor_sync(0xffffffffu, sq, o);
    }
    float mean = s * (1.0f/EMB);
    float var  = sq * (1.0f/EMB) - mean*mean;
    float rstd = rsqrtf(var + LN_EPS);
    const float4* g4 = (const float4*)g;
    const float4* b4 = (const float4*)b;
    #pragma unroll
    for (int i = 0; i < 4; i++) {
        float4 gg = g4[lane + 32*i], bb = b4[lane + 32*i];
        float4 o;
        o.x = (v[i].x - mean) * rstd * gg.x + bb.x;
        o.y = (v[i].y - mean) * rstd * gg.y + bb.y;
        o.z = (v[i].z - mean) * rstd * gg.z + bb.z;
        o.w = (v[i].w - mean) * rstd * gg.w + bb.w;
        if (MODE == 0) {
            ((float4*)(out + (size_t)tok * EMB))[lane + 32*i] = o;
        } else {
            size_t idx = (size_t)tok * EMB + (size_t)(lane + 32*i) * 4;
            __half h[4];
            h[0] = __float2half(o.x); h[1] = __float2half(o.y);
            h[2] = __float2half(o.z); h[3] = __float2half(o.w);
            *(uint2*)(ohi + idx) = *(uint2*)h;
        }
    }
}

// ---------------- kqv + prm_exp (8 tokens per block, 4 heads per pass) ----------------
#define SKQ_STRIDE 200
// sh_h 4096 | wk_t 12288 | wr_t 2048 | sbias 192 | skqv4 4*8*200=6400 | sxd4 64
#define K1_SMEM_FLOATS (4096 + 12288 + 2048 + 192 + 6400 + 64)
__global__ void kqv_prm_kernel(const float* __restrict__ hN, const float* __restrict__ kqv_w,
                               const float* __restrict__ kqv_b, const float* __restrict__ wrf,
                               float* __restrict__ gv, float* __restrict__ gkp,
                               float* __restrict__ gqp) {
    extern __shared__ float sm[];
    float* sh_h  = sm;                    // [8 tok][512]
    float* wk_t  = sm + 4096;             // [64 e][192 f]
    float* wr_t  = wk_t + 12288;          // [64 e][32 m]
    float* sbias = wr_t + 2048;           // [192]
    float* skqv4 = sbias + 192;           // [4 hd][8 tok][SKQ_STRIDE]
    float* sxd4  = skqv4 + 6400;          // [4 hd][16]
    int tid = threadIdx.x;
    size_t t0 = (size_t)blockIdx.x * 8;

    {
        const float4* src = (const float4*)(hN + t0 * EMB);
        float4* dst = (float4*)sh_h;
        #pragma unroll
        for (int i = 0; i < 4; i++) dst[tid + 256*i] = src[tid + 256*i];
    }
    #pragma unroll
    for (int i = 0; i < 12; i++) {
        int j = tid + 256*i;
        int f = j >> 4, e0 = (j & 15) << 2;
        float4 w4 = ((const float4*)kqv_w)[j];
        wk_t[(e0+0)*192 + f] = w4.x;
        wk_t[(e0+1)*192 + f] = w4.y;
        wk_t[(e0+2)*192 + f] = w4.z;
        wk_t[(e0+3)*192 + f] = w4.w;
    }
    #pragma unroll
    for (int i = 0; i < 2; i++) {
        int j = tid + 256*i;
        int m = j >> 4, e0 = (j & 15) << 2;
        float4 w4 = ((const float4*)wrf)[j];
        wr_t[(e0+0)*32 + m] = w4.x;
        wr_t[(e0+1)*32 + m] = w4.y;
        wr_t[(e0+2)*32 + m] = w4.z;
        wr_t[(e0+3)*32 + m] = w4.w;
    }
    if (tid < 192) sbias[tid] = kqv_b[tid];
    __syncthreads();

    int fg = tid & 63, tg = tid >> 6;
    int f0 = fg * 3, tokA = tg * 2;

    for (int hg = 0; hg < 2; hg++) {
        // ---- kqv: 3f x 2tok x 4heads register tile ----
        float acc[3][2][4];
        #pragma unroll
        for (int a = 0; a < 3; a++)
            #pragma unroll
            for (int t = 0; t < 2; t++)
                #pragma unroll
                for (int d = 0; d < 4; d++) acc[a][t][d] = 0.f;
        const float* hbase = sh_h + hg * 4 * 64 + tokA * 512;
        #pragma unroll 4
        for (int e = 0; e < 64; e++) {
            float w0 = wk_t[e*192 + f0];
            float w1 = wk_t[e*192 + f0 + 1];
            float w2 = wk_t[e*192 + f0 + 2];
            #pragma unroll
            for (int d = 0; d < 4; d++) {
                float h0 = hbase[d*64 + e];
                float h1 = hbase[512 + d*64 + e];
                acc[0][0][d] += w0*h0; acc[0][1][d] += w0*h1;
                acc[1][0][d] += w1*h0; acc[1][1][d] += w1*h1;
                acc[2][0][d] += w2*h0; acc[2][1][d] += w2*h1;
            }
        }
        #pragma unroll
        for (int d = 0; d < 4; d++)
            #pragma unroll
            for (int t = 0; t < 2; t++) {
                float* row = skqv4 + d*8*SKQ_STRIDE + (tokA+t)*SKQ_STRIDE;
                row[f0+0] = acc[0][t][d] + sbias[f0+0];
                row[f0+1] = acc[1][t][d] + sbias[f0+1];
                row[f0+2] = acc[2][t][d] + sbias[f0+2];
            }
        __syncthreads();

        // ---- v write: 4*8*64 = 2048 values ----
        #pragma unroll
        for (int i = 0; i < 8; i++) {
            int idx = tid + 256*i;
            int hd4 = idx >> 9, tok = (idx >> 6) & 7, e = idx & 63;
            gv[(((t0 + tok) * HEADS) + hg*4 + hd4) * ES + e] =
                skqv4[hd4*8*SKQ_STRIDE + tok*SKQ_STRIDE + 128 + e];
        }
        // ---- xd: 4 hd x 8 tok x 2 which ----
        if (tid < 64) {
            int hd4 = tid >> 4, r = tid & 15, tok = r >> 1, which = r & 1;
            const float* z = skqv4 + hd4*8*SKQ_STRIDE + tok*SKQ_STRIDE + which*64;
            float s = 0.f;
            #pragma unroll 8
            for (int e = 0; e < 64; e++) { float zz = z[e]; s += zz*zz; }
            sxd4[hd4*16 + r] = 0.5f * s;
        }
        __syncthreads();

        // ---- wtx + exp: 512 slots x 4m each ----
        #pragma unroll
        for (int i = 0; i < 2; i++) {
            int sidx = tid + 256*i;
            int mg = sidx & 7, which = (sidx >> 3) & 1, tok = (sidx >> 4) & 7, hd4 = sidx >> 7;
            int m0 = mg * 4;
            const float* z = skqv4 + hd4*8*SKQ_STRIDE + tok*SKQ_STRIDE + which*64;
            float a0 = 0.f, a1 = 0.f, a2 = 0.f, a3 = 0.f;
            #pragma unroll 8
            for (int e = 0; e < 64; e++) {
                float zv = z[e];
                float4 w4 = *(const float4*)&wr_t[e*32 + m0];
                a0 += zv*w4.x; a1 += zv*w4.y; a2 += zv*w4.z; a3 += zv*w4.w;
            }
            float xdv = sxd4[hd4*16 + tok*2 + which];
            float4 o;
            o.x = expf(a0 - xdv) * 0.17677669529663689f;
            o.y = expf(a1 - xdv) * 0.17677669529663689f;
            o.z = expf(a2 - xdv) * 0.17677669529663689f;
            o.w = expf(a3 - xdv) * 0.17677669529663689f;
            float* dst = which ? gqp : gkp;
            *(float4*)&dst[(((t0 + tok) * HEADS) + hg*4 + hd4) * MF + m0] = o;
        }
        __syncthreads();
    }
}

// ---------------- kptv / ksum partial reduction over T ----------------
__global__ void kpt_kernel(const float* __restrict__ gv, const float* __restrict__ gkp,
                           float* __restrict__ part_kptv, float* __restrict__ part_ksum) {
    int chunk = blockIdx.x;
    int bh = blockIdx.y;
    int b = bh >> 3, h = bh & 7;
    __shared__ float sv[16][64];
    __shared__ float skp[16][32];
    int tid = threadIdx.x, lane = tid & 31, wid = tid >> 5;
    float acc[8] = {0,0,0,0,0,0,0,0};
    float ks = 0.f;
    int t0 = chunk * 256;
    for (int st = 0; st < 16; st++) {
        int s0 = t0 + st * 16;
        __syncthreads();
        #pragma unroll
        for (int i = 0; i < 4; i++) {
            int idx = tid + 256*i;
            int s = idx >> 6, e = idx & 63;
            sv[s][e] = gv[((((size_t)b*TQ + s0 + s) * HEADS) + h) * ES + e];
        }
        #pragma unroll
        for (int i = 0; i < 2; i++) {
            int idx = tid + 256*i;
            int s = idx >> 5, m = idx & 31;
            skp[s][m] = gkp[((((size_t)b*TQ + s0 + s) * HEADS) + h) * MF + m];
        }
        __syncthreads();
        #pragma unroll
        for (int s = 0; s < 16; s++) {
            float kv = skp[s][lane];
            float4 va = *(const float4*)&sv[s][wid*8];
            float4 vb = *(const float4*)&sv[s][wid*8 + 4];
            acc[0] += va.x*kv; acc[1] += va.y*kv; acc[2] += va.z*kv; acc[3] += va.w*kv;
            acc[4] += vb.x*kv; acc[5] += vb.y*kv; acc[6] += vb.z*kv; acc[7] += vb.w*kv;
            if (wid == 0) ks += kv;
        }
    }
    size_t base = ((size_t)(chunk*64 + bh)) * (ES*MF);
    #pragma unroll
    for (int j = 0; j < 8; j++)
        part_kptv[base + (wid*8 + j)*MF + lane] = acc[j];
    if (wid == 0) part_ksum[(chunk*64 + bh)*MF + lane] = ks;
}

__global__ void reduce_kernel(const float* __restrict__ pk, const float* __restrict__ ps,
                              float* __restrict__ kptv, float* __restrict__ ksum) {
    int bid = blockIdx.x;
    if (bid < 512) {
        int idx = bid * 256 + threadIdx.x;
        int bh = idx >> 11;
        float s = 0.f;
        #pragma unroll
        for (int c = 0; c < 16; c++) s += pk[((size_t)(c*64 + bh)) * 2048 + (idx & 2047)];
        kptv[idx] = s;
    } else {
        #pragma unroll
        for (int j = 0; j < 8; j++) {
            int idx = threadIdx.x * 8 + j;
            int bh = idx >> 5, m = idx & 31;
            float s = 0.f;
            #pragma unroll
            for (int c = 0; c < 16; c++) s += ps[(c*64 + bh)*MF + m];
            ksum[idx] = s;
        }
    }
}

// ---------------- y = (qp . kptv) / D  -> fp16 ----------------
__global__ void y_kernel(const float* __restrict__ gqp, const float* __restrict__ kptv,
                         const float* __restrict__ ksum, __half* __restrict__ yh) {
    int bh = blockIdx.y, b = bh >> 3, h = bh & 7;
    __shared__ float sk[64*33];
    __shared__ float sks[32];
    int tid = threadIdx.x, lane = tid & 31, wid = tid >> 5;
    #pragma unroll
    for (int i = 0; i < 8; i++) {
        int idx = tid + 256*i;
        sk[(idx >> 5)*33 + (idx & 31)] = kptv[(size_t)bh*2048 + idx];
    }
    if (tid < 32) sks[tid] = ksum[bh*32 + tid];
    __syncthreads();
    float ksv = sks[lane];
    for (int it = 0; it < 32; it++) {
        int t = blockIdx.x * 256 + wid * 32 + it;
        float qpv = gqp[((((size_t)b*TQ + t) * HEADS) + h) * MF + lane];
        float d = qpv * ksv;
        #pragma unroll
        for (int o = 16; o; o >>= 1) d += __shfl_xor_sync(0xffffffffu, d, o);
        float a0 = 0.f, a1 = 0.f;
        #pragma unroll
        for (int m = 0; m < 32; m++) {
            float qm = __shfl_sync(0xffffffffu, qpv, m);
            a0 += qm * sk[lane*33 + m];
            a1 += qm * sk[(lane+32)*33 + m];
        }
        float inv = 1.0f / d;
        size_t off = ((size_t)b*TQ + t) * EMB + h * ES;
        yh[off + lane]      = __float2half(a0 * inv);
        yh[off + lane + 32] = __float2half(a1 * inv);
    }
}

// ============== mma.sync fp16 GEMM (fp32 accum), 3-stage cp.async pipeline ==============
// 128x128 CTA tile, 8 warps (4m x 2n), warp tile 32x64, chunk K=64.
// 128B rows, canonical SW128 swizzle: chunk' = chunk ^ (row&7). 2 CTAs/SM.
#define PLANE_BYTES 16384                 // 128 rows x 128B
#define BUF_BYTES (2*PLANE_BYTES)         // 32768
#define GEMM_SMEM (3*BUF_BYTES)           // 98304

#define SWZ_ADDR(base, row, chunk) \
    ((base) + (uint32_t)(row)*128u + (uint32_t)(((chunk) ^ ((row)&7)) << 4))

template<int EPI>
__global__ __launch_bounds__(256, 2)
void gemm_mma(const __half* __restrict__ Ah, const __half* __restrict__ Bh,
              const float* __restrict__ bias, const float* __restrict__ res,
              float* __restrict__ Cf, __half* __restrict__ Chi, int N, int K) {
    extern __shared__ char gsm[];
    uint32_t sb = smem_to_u32(gsm);
    int tid = threadIdx.x, lane = tid & 31, wid = tid >> 5;
    int rowBase = blockIdx.y * 128, colBase = blockIdx.x * 128;

    int wm = wid & 3, wn = wid >> 2;      // 4x2 warp grid
    int m0 = wm * 32, n0 = wn * 64;

    float acc[2][8][4];
    #pragma unroll
    for (int i = 0; i < 2; i++)
        #pragma unroll
        for (int j = 0; j < 8; j++)
            #pragma unroll
            for (int q = 0; q < 4; q++) acc[i][j][q] = 0.f;

    int arow_l = (lane & 15);
    int acb    = (lane >> 4);
    int brow_l = (lane & 7) + ((lane >> 4) << 3);
    int bcb    = (lane >> 3) & 1;

    auto load_chunk = [&](int buf, int k0) {
        uint32_t sbase = sb + buf * BUF_BYTES;
        int row = tid >> 1, c0 = (tid & 1) * 4;
        size_t goA = (size_t)(rowBase + row) * K + k0 + c0 * 8;
        size_t goB = (size_t)(colBase + row) * K + k0 + c0 * 8;
        #pragma unroll
        for (int j = 0; j < 4; j++) {
            uint32_t so = SWZ_ADDR(sbase, row, c0 + j);
            cp_async16(so,               Ah + goA + j * 8);
            cp_async16(PLANE_BYTES + so, Bh + goB + j * 8);
        }
    };

    int NC = K >> 6;
    load_chunk(0, 0);
    CP_COMMIT();
    load_chunk(1, 64);
    CP_COMMIT();

    int bufc = 0, bufn = 2;
    for (int c = 0; c < NC; c++) {
        if (c + 2 < NC) {
            load_chunk(bufn, (c + 2) << 6);
            CP_COMMIT();
            CP_WAIT2();
        } else if (c + 1 < NC) {
            CP_WAIT1();
        } else {
            CP_WAIT0();
        }
        __syncthreads();

        uint32_t pA = sb + bufc * BUF_BYTES;
        #pragma unroll
        for (int ks = 0; ks < 4; ks++) {
            uint32_t ah[2][4];
            #pragma unroll
            for (int mt = 0; mt < 2; mt++) {
                int ar = m0 + mt * 16 + arow_l;
                uint32_t ad = SWZ_ADDR(pA, ar, ks * 2 + acb);
                ldsm_x4(ah[mt][0], ah[mt][1], ah[mt][2], ah[mt][3], ad);
            }
            #pragma unroll
            for (int ng = 0; ng < 4; ng++) {
                int br = n0 + ng * 16 + brow_l;
                uint32_t bd = SWZ_ADDR(pA + PLANE_BYTES, br, ks * 2 + bcb);
                uint32_t bh2[2][2];
                ldsm_x4(bh2[0][0], bh2[0][1], bh2[1][0], bh2[1][1], bd);
                #pragma unroll
                for (int mt = 0; mt < 2; mt++)
                    #pragma unroll
                    for (int j = 0; j < 2; j++)
                        mma_f16(acc[mt][2*ng + j], ah[mt], bh2[j]);
            }
        }
        __syncthreads();
        bufc = (bufc + 1 == 3) ? 0 : bufc + 1;
        bufn = (bufn + 1 == 3) ? 0 : bufn + 1;
    }

    // ---- epilogue ----
    int rbase = rowBase + m0 + (lane >> 2);
    int cbase = colBase + n0 + (lane & 3) * 2;
    #pragma unroll
    for (int mt = 0; mt < 2; mt++) {
        #pragma unroll
        for (int half = 0; half < 2; half++) {
            int row = rbase + mt * 16 + half * 8;
            if (EPI == 0) {
                float* crow = Cf + (size_t)row * N;
                const float* rrow = res + (size_t)row * N;
                #pragma unroll
                for (int nt = 0; nt < 8; nt++) {
                    int col = cbase + nt * 8;
                    float2 o;
                    o.x = acc[mt][nt][half*2+0] + bias[col]   + rrow[col];
                    o.y = acc[mt][nt][half*2+1] + bias[col+1] + rrow[col+1];
                    *(float2*)(crow + col) = o;
                }
            } else {
                __half* hrow = Chi + (size_t)row * N;
                #pragma unroll
                for (int nt = 0; nt < 8; nt++) {
                    int col = cbase + nt * 8;
                    float v0 = acc[mt][nt][half*2+0] + bias[col];
                    float v1 = acc[mt][nt][half*2+1] + bias[col+1];
                    v0 = 0.5f * v0 * (1.0f + erff(v0 * 0.70710678118654752f));
                    v1 = 0.5f * v1 * (1.0f + erff(v1 * 0.70710678118654752f));
                    __half hh[2] = {__float2half(v0), __float2half(v1)};
                    *(uint32_t*)(hrow + col) = *(uint32_t*)hh;
                }
            }
        }
    }
}

// ---------------- launch ----------------
extern "C" void kernel_launch(void* const* d_in, const int* in_sizes, int n_in,
                              void* d_out, int out_size) {
    const float* x      = (const float*)d_in[0];
    const float* wrf    = (const float*)d_in[1];
    const float* kqv_w  = (const float*)d_in[2];
    const float* kqv_b  = (const float*)d_in[3];
    const float* proj_w = (const float*)d_in[4];
    const float* proj_b = (const float*)d_in[5];
    const float* ln1_g  = (const float*)d_in[6];
    const float* ln1_b  = (const float*)d_in[7];
    const float* ln2_g  = (const float*)d_in[8];
    const float* ln2_b  = (const float*)d_in[9];
    const float* mlp_w1 = (const float*)d_in[10];
    const float* mlp_b1 = (const float*)d_in[11];
    const float* mlp_w2 = (const float*)d_in[12];
    const float* mlp_b2 = (const float*)d_in[13];
    float* out = (float*)d_out;

    float *p_h2, *p_v, *p_qp, *p_kp, *p_pk, *p_ps, *p_kptv, *p_ksum, *p_x1;
    __half *p_h2h, *p_yh, *p_hidh, *p_pwh, *p_w1h, *p_w2h;
    cudaGetSymbolAddress((void**)&p_h2,   g_h2);
    cudaGetSymbolAddress((void**)&p_v,    g_v);
    cudaGetSymbolAddress((void**)&p_qp,   g_qp);
    cudaGetSymbolAddress((void**)&p_kp,   g_kp);
    cudaGetSymbolAddress((void**)&p_pk,   g_kptv_part);
    cudaGetSymbolAddress((void**)&p_ps,   g_ksum_part);
    cudaGetSymbolAddress((void**)&p_kptv, g_kptv);
    cudaGetSymbolAddress((void**)&p_ksum, g_ksum);
    cudaGetSymbolAddress((void**)&p_x1,   g_x1);
    cudaGetSymbolAddress((void**)&p_h2h,  g_h2h);
    cudaGetSymbolAddress((void**)&p_yh,   g_yh);
    cudaGetSymbolAddress((void**)&p_hidh, g_hidh);
    cudaGetSymbolAddress((void**)&p_pwh,  g_pwh);
    cudaGetSymbolAddress((void**)&p_w1h,  g_w1h);
    cudaGetSymbolAddress((void**)&p_w2h,  g_w2h);

    const size_t k1_smem = (size_t)K1_SMEM_FLOATS * sizeof(float);   // ~98KB
    cudaFuncSetAttribute(kqv_prm_kernel, cudaFuncAttributeMaxDynamicSharedMemorySize,
                         (int)k1_smem);
    cudaFuncSetAttribute(gemm_mma<0>, cudaFuncAttributeMaxDynamicSharedMemorySize, GEMM_SMEM);
    cudaFuncSetAttribute(gemm_mma<1>, cudaFuncAttributeMaxDynamicSharedMemorySize, GEMM_SMEM);

    // 0. weight fp16 rounds
    cvt_h_kernel<<<(EMB*EMB/4 + 255)/256, 256>>>(proj_w, p_pwh, EMB*EMB/4);
    cvt_h_kernel<<<(HID*EMB/4 + 255)/256, 256>>>(mlp_w1, p_w1h, HID*EMB/4);
    cvt_h_kernel<<<(EMB*HID/4 + 255)/256, 256>>>(mlp_w2, p_w2h, EMB*HID/4);
    // 1. LN1
    ln_kernel<0><<<NTOK/8, 256>>>(x, ln1_g, ln1_b, p_h2, nullptr);
    // 2. kqv + prm_exp
    kqv_prm_kernel<<<NTOK/8, 256, k1_smem>>>(p_h2, kqv_w, kqv_b, wrf, p_v, p_kp, p_qp);
    // 3-4. kptv/ksum reduction over T
    kpt_kernel<<<dim3(16, 64), 256>>>(p_v, p_kp, p_pk, p_ps);
    reduce_kernel<<<513, 256>>>(p_pk, p_ps, p_kptv, p_ksum);
    // 5. y (fp16)
    y_kernel<<<dim3(TQ/256, 64), 256>>>(p_qp, p_kptv, p_ksum, p_yh);
    // 6. attn proj + residual -> x1 (fp32)
    gemm_mma<0><<<dim3(EMB/128, NTOK/128), 256, GEMM_SMEM>>>(
        p_yh, p_pwh, proj_b, x, p_x1, nullptr, EMB, EMB);
    // 7. LN2 -> fp16
    ln_kernel<1><<<NTOK/8, 256>>>(p_x1, ln2_g, ln2_b, nullptr, p_h2h);
    // 8. mlp1 + gelu -> hid (fp16)
    gemm_mma<1><<<dim3(HID/128, NTOK/128), 256, GEMM_SMEM>>>(
        p_h2h, p_w1h, mlp_b1, nullptr, nullptr, p_hidh, HID, EMB);
    // 9. mlp2 + residual -> out (fp32)
    gemm_mma<0><<<dim3(EMB/128, NTOK/128), 256, GEMM_SMEM>>>(
        p_hidh, p_w2h, mlp_b2, p_x1, out, nullptr, EMB, HID);
}

// round 9
// speedup vs baseline: 3.7199x; 1.0396x over previous
#include <cuda_runtime.h>
#include <cuda_fp16.h>
#include <math.h>
#include <stdint.h>

// Problem constants
#define BQ 8
#define TQ 4096
#define NTOK (BQ*TQ)          // 32768 tokens
#define EMB 512
#define HEADS 8
#define ES 64
#define MF 32                 // random features
#define HID (4*EMB)           // 2048
#define LN_EPS 1e-5f

__device__ __forceinline__ uint32_t smem_to_u32(const void* smem_ptr) {
    uint32_t addr;
    asm("{ .reg .u64 tmp; cvta.to.shared.u64 tmp, %1; cvt.u32.u64 %0, tmp; }"
        : "=r"(addr) : "l"(smem_ptr));
    return addr;
}

__device__ __forceinline__ void cp_async16(uint32_t saddr, const void* gaddr) {
    asm volatile("cp.async.cg.shared.global [%0], [%1], 16;" :: "r"(saddr), "l"(gaddr));
}
#define CP_COMMIT() asm volatile("cp.async.commit_group;" ::: "memory")
#define CP_WAIT0()  asm volatile("cp.async.wait_group 0;" ::: "memory")
#define CP_WAIT1()  asm volatile("cp.async.wait_group 1;" ::: "memory")

__device__ __forceinline__ void ldsm_x4(uint32_t& r0, uint32_t& r1, uint32_t& r2, uint32_t& r3,
                                        uint32_t addr) {
    asm volatile("ldmatrix.sync.aligned.m8n8.x4.shared.b16 {%0,%1,%2,%3}, [%4];"
        : "=r"(r0), "=r"(r1), "=r"(r2), "=r"(r3) : "r"(addr));
}

__device__ __forceinline__ void mma_f16(float* c, const uint32_t* a, const uint32_t* b) {
    asm volatile(
        "mma.sync.aligned.m16n8k16.row.col.f32.f16.f16.f32 "
        "{%0,%1,%2,%3}, {%4,%5,%6,%7}, {%8,%9}, {%0,%1,%2,%3};"
        : "+f"(c[0]), "+f"(c[1]), "+f"(c[2]), "+f"(c[3])
        : "r"(a[0]), "r"(a[1]), "r"(a[2]), "r"(a[3]), "r"(b[0]), "r"(b[1]));
}

// -------- scratch (device globals; no runtime allocation) --------
__device__ float g_v[(size_t)NTOK*HEADS*ES];
__device__ float g_qp[(size_t)NTOK*HEADS*MF];
__device__ float g_kp[(size_t)NTOK*HEADS*MF];
__device__ float g_kptv_part[16*64*ES*MF];
__device__ float g_ksum_part[16*64*MF];
__device__ float g_kptv[64*ES*MF];
__device__ float g_ksum[64*MF];
__device__ float g_x1[(size_t)NTOK*EMB];
// fp16 activations + weights (single plane each)
__device__ __align__(16) __half g_h2h[(size_t)NTOK*EMB];
__device__ __align__(16) __half g_yh[(size_t)NTOK*EMB];
__device__ __align__(16) __half g_hidh[(size_t)NTOK*HID];
__device__ __align__(16) __half g_pwh[EMB*EMB];      // 256K elems
__device__ __align__(16) __half g_w1h[HID*EMB];      // 1M elems
__device__ __align__(16) __half g_w2h[EMB*HID];      // 1M elems

// ---------------- fused weight fp16 conversion (all 3 weights) ----------------
// float4 index ranges: [0, 64K) proj | [64K, 320K) w1 | [320K, 576K) w2
#define CVT_N4 (65536 + 262144 + 262144)
__global__ void cvt_all_kernel(const float* __restrict__ pw, const float* __restrict__ w1,
                               const float* __restrict__ w2, __half* __restrict__ pwh,
                               __half* __restrict__ w1h, __half* __restrict__ w2h) {
    int i = blockIdx.x * 256 + threadIdx.x;
    if (i >= CVT_N4) return;
    const float* src;
    __half* dst;
    int j;
    if (i < 65536)       { src = pw; dst = pwh; j = i; }
    else if (i < 327680) { src = w1; dst = w1h; j = i - 65536; }
    else                 { src = w2; dst = w2h; j = i - 327680; }
    float4 v = ((const float4*)src)[j];
    __half h[4];
    h[0] = __float2half(v.x); h[1] = __float2half(v.y);
    h[2] = __float2half(v.z); h[3] = __float2half(v.w);
    *(uint2*)(dst + (size_t)j*4) = *(uint2*)h;
}

// ---------------- LayerNorm (LN2): warp per token, fp16 out ----------------
__global__ void ln2_kernel(const float* __restrict__ x, const float* __restrict__ g,
                           const float* __restrict__ b, __half* __restrict__ ohi) {
    int tok  = blockIdx.x * 8 + (threadIdx.x >> 5);
    int lane = threadIdx.x & 31;
    const float4* xr = (const float4*)(x + (size_t)tok * EMB);
    float4 v[4];
    float s = 0.f, sq = 0.f;
    #pragma unroll
    for (int i = 0; i < 4; i++) {
        v[i] = xr[lane + 32*i];
        s  += v[i].x + v[i].y + v[i].z + v[i].w;
        sq += v[i].x*v[i].x + v[i].y*v[i].y + v[i].z*v[i].z + v[i].w*v[i].w;
    }
    #pragma unroll
    for (int o = 16; o; o >>= 1) {
        s  += __shfl_xor_sync(0xffffffffu, s,  o);
        sq += __shfl_xor_sync(0xffffffffu, sq, o);
    }
    float mean = s * (1.0f/EMB);
    float var  = sq * (1.0f/EMB) - mean*mean;
    float rstd = rsqrtf(var + LN_EPS);
    const float4* g4 = (const float4*)g;
    const float4* b4 = (const float4*)b;
    #pragma unroll
    for (int i = 0; i < 4; i++) {
        float4 gg = g4[lane + 32*i], bb = b4[lane + 32*i];
        size_t idx = (size_t)tok * EMB + (size_t)(lane + 32*i) * 4;
        __half h[4];
        h[0] = __float2half((v[i].x - mean) * rstd * gg.x + bb.x);
        h[1] = __float2half((v[i].y - mean) * rstd * gg.y + bb.y);
        h[2] = __float2half((v[i].z - mean) * rstd * gg.z + bb.z);
        h[3] = __float2half((v[i].w - mean) * rstd * gg.w + bb.w);
        *(uint2*)(ohi + idx) = *(uint2*)h;
    }
}

// ---------------- fused LN1 + kqv + prm_exp (8 tokens per block, 4 heads/pass) ----------------
#define SKQ_STRIDE 200
// sh_h 4096 | wk_t 12288 | wr_t 2048 | sbias 192 | skqv4 6400 | sxd4 64
#define K1_SMEM_FLOATS (4096 + 12288 + 2048 + 192 + 6400 + 64)
__global__ void kqv_prm_kernel(const float* __restrict__ xg, const float* __restrict__ ln1_g,
                               const float* __restrict__ ln1_b,
                               const float* __restrict__ kqv_w,
                               const float* __restrict__ kqv_b, const float* __restrict__ wrf,
                               float* __restrict__ gv, float* __restrict__ gkp,
                               float* __restrict__ gqp) {
    extern __shared__ float sm[];
    float* sh_h  = sm;                    // [8 tok][512] normalized
    float* wk_t  = sm + 4096;             // [64 e][192 f]
    float* wr_t  = wk_t + 12288;          // [64 e][32 m]
    float* sbias = wr_t + 2048;           // [192]
    float* skqv4 = sbias + 192;           // [4 hd][8 tok][SKQ_STRIDE]
    float* sxd4  = skqv4 + 6400;          // [4 hd][16]
    int tid = threadIdx.x;
    size_t t0 = (size_t)blockIdx.x * 8;

    // ---- fused LN1: warp per token ----
    {
        int tok = tid >> 5, lane = tid & 31;
        const float4* xr = (const float4*)(xg + (t0 + tok) * EMB);
        float4 v[4];
        float s = 0.f, sq = 0.f;
        #pragma unroll
        for (int i = 0; i < 4; i++) {
            v[i] = xr[lane + 32*i];
            s  += v[i].x + v[i].y + v[i].z + v[i].w;
            sq += v[i].x*v[i].x + v[i].y*v[i].y + v[i].z*v[i].z + v[i].w*v[i].w;
        }
        #pragma unroll
        for (int o = 16; o; o >>= 1) {
            s  += __shfl_xor_sync(0xffffffffu, s,  o);
            sq += __shfl_xor_sync(0xffffffffu, sq, o);
        }
        float mean = s * (1.0f/EMB);
        float var  = sq * (1.0f/EMB) - mean*mean;
        float rstd = rsqrtf(var + LN_EPS);
        const float4* g4 = (const float4*)ln1_g;
        const float4* b4 = (const float4*)ln1_b;
        float4* hrow = (float4*)(sh_h + tok * 512);
        #pragma unroll
        for (int i = 0; i < 4; i++) {
            float4 gg = g4[lane + 32*i], bb = b4[lane + 32*i];
            float4 o;
            o.x = (v[i].x - mean) * rstd * gg.x + bb.x;
            o.y = (v[i].y - mean) * rstd * gg.y + bb.y;
            o.z = (v[i].z - mean) * rstd * gg.z + bb.z;
            o.w = (v[i].w - mean) * rstd * gg.w + bb.w;
            hrow[lane + 32*i] = o;
        }
    }
    // ---- weights to smem ----
    #pragma unroll
    for (int i = 0; i < 12; i++) {
        int j = tid + 256*i;
        int f = j >> 4, e0 = (j & 15) << 2;
        float4 w4 = ((const float4*)kqv_w)[j];
        wk_t[(e0+0)*192 + f] = w4.x;
        wk_t[(e0+1)*192 + f] = w4.y;
        wk_t[(e0+2)*192 + f] = w4.z;
        wk_t[(e0+3)*192 + f] = w4.w;
    }
    #pragma unroll
    for (int i = 0; i < 2; i++) {
        int j = tid + 256*i;
        int m = j >> 4, e0 = (j & 15) << 2;
        float4 w4 = ((const float4*)wrf)[j];
        wr_t[(e0+0)*32 + m] = w4.x;
        wr_t[(e0+1)*32 + m] = w4.y;
        wr_t[(e0+2)*32 + m] = w4.z;
        wr_t[(e0+3)*32 + m] = w4.w;
    }
    if (tid < 192) sbias[tid] = kqv_b[tid];
    __syncthreads();

    int fg = tid & 63, tg = tid >> 6;
    int f0 = fg * 3, tokA = tg * 2;

    for (int hg = 0; hg < 2; hg++) {
        float acc[3][2][4];
        #pragma unroll
        for (int a = 0; a < 3; a++)
            #pragma unroll
            for (int t = 0; t < 2; t++)
                #pragma unroll
                for (int d = 0; d < 4; d++) acc[a][t][d] = 0.f;
        const float* hbase = sh_h + hg * 4 * 64 + tokA * 512;
        #pragma unroll 4
        for (int e = 0; e < 64; e++) {
            float w0 = wk_t[e*192 + f0];
            float w1 = wk_t[e*192 + f0 + 1];
            float w2 = wk_t[e*192 + f0 + 2];
            #pragma unroll
            for (int d = 0; d < 4; d++) {
                float h0 = hbase[d*64 + e];
                float h1 = hbase[512 + d*64 + e];
                acc[0][0][d] += w0*h0; acc[0][1][d] += w0*h1;
                acc[1][0][d] += w1*h0; acc[1][1][d] += w1*h1;
                acc[2][0][d] += w2*h0; acc[2][1][d] += w2*h1;
            }
        }
        #pragma unroll
        for (int d = 0; d < 4; d++)
            #pragma unroll
            for (int t = 0; t < 2; t++) {
                float* row = skqv4 + d*8*SKQ_STRIDE + (tokA+t)*SKQ_STRIDE;
                row[f0+0] = acc[0][t][d] + sbias[f0+0];
                row[f0+1] = acc[1][t][d] + sbias[f0+1];
                row[f0+2] = acc[2][t][d] + sbias[f0+2];
            }
        __syncthreads();

        #pragma unroll
        for (int i = 0; i < 8; i++) {
            int idx = tid + 256*i;
            int hd4 = idx >> 9, tok = (idx >> 6) & 7, e = idx & 63;
            gv[(((t0 + tok) * HEADS) + hg*4 + hd4) * ES + e] =
                skqv4[hd4*8*SKQ_STRIDE + tok*SKQ_STRIDE + 128 + e];
        }
        if (tid < 64) {
            int hd4 = tid >> 4, r = tid & 15, tok = r >> 1, which = r & 1;
            const float* z = skqv4 + hd4*8*SKQ_STRIDE + tok*SKQ_STRIDE + which*64;
            float s = 0.f;
            #pragma unroll 8
            for (int e = 0; e < 64; e++) { float zz = z[e]; s += zz*zz; }
            sxd4[hd4*16 + r] = 0.5f * s;
        }
        __syncthreads();

        #pragma unroll
        for (int i = 0; i < 2; i++) {
            int sidx = tid + 256*i;
            int mg = sidx & 7, which = (sidx >> 3) & 1, tok = (sidx >> 4) & 7, hd4 = sidx >> 7;
            int m0 = mg * 4;
            const float* z = skqv4 + hd4*8*SKQ_STRIDE + tok*SKQ_STRIDE + which*64;
            float a0 = 0.f, a1 = 0.f, a2 = 0.f, a3 = 0.f;
            #pragma unroll 8
            for (int e = 0; e < 64; e++) {
                float zv = z[e];
                float4 w4 = *(const float4*)&wr_t[e*32 + m0];
                a0 += zv*w4.x; a1 += zv*w4.y; a2 += zv*w4.z; a3 += zv*w4.w;
            }
            float xdv = sxd4[hd4*16 + tok*2 + which];
            float4 o;
            o.x = expf(a0 - xdv) * 0.17677669529663689f;
            o.y = expf(a1 - xdv) * 0.17677669529663689f;
            o.z = expf(a2 - xdv) * 0.17677669529663689f;
            o.w = expf(a3 - xdv) * 0.17677669529663689f;
            float* dst = which ? gqp : gkp;
            *(float4*)&dst[(((t0 + tok) * HEADS) + hg*4 + hd4) * MF + m0] = o;
        }
        __syncthreads();
    }
}

// ---------------- kptv / ksum partial reduction over T ----------------
__global__ void kpt_kernel(const float* __restrict__ gv, const float* __restrict__ gkp,
                           float* __restrict__ part_kptv, float* __restrict__ part_ksum) {
    int chunk = blockIdx.x;
    int bh = blockIdx.y;
    int b = bh >> 3, h = bh & 7;
    __shared__ float sv[16][64];
    __shared__ float skp[16][32];
    int tid = threadIdx.x, lane = tid & 31, wid = tid >> 5;
    float acc[8] = {0,0,0,0,0,0,0,0};
    float ks = 0.f;
    int t0 = chunk * 256;
    for (int st = 0; st < 16; st++) {
        int s0 = t0 + st * 16;
        __syncthreads();
        #pragma unroll
        for (int i = 0; i < 4; i++) {
            int idx = tid + 256*i;
            int s = idx >> 6, e = idx & 63;
            sv[s][e] = gv[((((size_t)b*TQ + s0 + s) * HEADS) + h) * ES + e];
        }
        #pragma unroll
        for (int i = 0; i < 2; i++) {
            int idx = tid + 256*i;
            int s = idx >> 5, m = idx & 31;
            skp[s][m] = gkp[((((size_t)b*TQ + s0 + s) * HEADS) + h) * MF + m];
        }
        __syncthreads();
        #pragma unroll
        for (int s = 0; s < 16; s++) {
            float kv = skp[s][lane];
            float4 va = *(const float4*)&sv[s][wid*8];
            float4 vb = *(const float4*)&sv[s][wid*8 + 4];
            acc[0] += va.x*kv; acc[1] += va.y*kv; acc[2] += va.z*kv; acc[3] += va.w*kv;
            acc[4] += vb.x*kv; acc[5] += vb.y*kv; acc[6] += vb.z*kv; acc[7] += vb.w*kv;
            if (wid == 0) ks += kv;
        }
    }
    size_t base = ((size_t)(chunk*64 + bh)) * (ES*MF);
    #pragma unroll
    for (int j = 0; j < 8; j++)
        part_kptv[base + (wid*8 + j)*MF + lane] = acc[j];
    if (wid == 0) part_ksum[(chunk*64 + bh)*MF + lane] = ks;
}

__global__ void reduce_kernel(const float* __restrict__ pk, const float* __restrict__ ps,
                              float* __restrict__ kptv, float* __restrict__ ksum) {
    int bid = blockIdx.x;
    if (bid < 512) {
        int idx = bid * 256 + threadIdx.x;
        int bh = idx >> 11;
        float s = 0.f;
        #pragma unroll
        for (int c = 0; c < 16; c++) s += pk[((size_t)(c*64 + bh)) * 2048 + (idx & 2047)];
        kptv[idx] = s;
    } else {
        #pragma unroll
        for (int j = 0; j < 8; j++) {
            int idx = threadIdx.x * 8 + j;
            int bh = idx >> 5, m = idx & 31;
            float s = 0.f;
            #pragma unroll
            for (int c = 0; c < 16; c++) s += ps[(c*64 + bh)*MF + m];
            ksum[idx] = s;
        }
    }
}

// ---------------- y = (qp . kptv) / D  -> fp16 ----------------
__global__ void y_kernel(const float* __restrict__ gqp, const float* __restrict__ kptv,
                         const float* __restrict__ ksum, __half* __restrict__ yh) {
    int bh = blockIdx.y, b = bh >> 3, h = bh & 7;
    __shared__ float sk[64*33];
    __shared__ float sks[32];
    int tid = threadIdx.x, lane = tid & 31, wid = tid >> 5;
    #pragma unroll
    for (int i = 0; i < 8; i++) {
        int idx = tid + 256*i;
        sk[(idx >> 5)*33 + (idx & 31)] = kptv[(size_t)bh*2048 + idx];
    }
    if (tid < 32) sks[tid] = ksum[bh*32 + tid];
    __syncthreads();
    float ksv = sks[lane];
    for (int it = 0; it < 32; it++) {
        int t = blockIdx.x * 256 + wid * 32 + it;
        float qpv = gqp[((((size_t)b*TQ + t) * HEADS) + h) * MF + lane];
        float d = qpv * ksv;
        #pragma unroll
        for (int o = 16; o; o >>= 1) d += __shfl_xor_sync(0xffffffffu, d, o);
        float a0 = 0.f, a1 = 0.f;
        #pragma unroll
        for (int m = 0; m < 32; m++) {
            float qm = __shfl_sync(0xffffffffu, qpv, m);
            a0 += qm * sk[lane*33 + m];
            a1 += qm * sk[(lane+32)*33 + m];
        }
        float inv = 1.0f / d;
        size_t off = ((size_t)b*TQ + t) * EMB + h * ES;
        yh[off + lane]      = __float2half(a0 * inv);
        yh[off + lane + 32] = __float2half(a1 * inv);
    }
}

// ============== mma.sync fp16 GEMM (fp32 accum), 3-stage, ONE sync per chunk ==============
// 128x128 CTA tile, 8 warps (4m x 2n), warp tile 32x64, chunk K=64.
// 128B rows, canonical SW128 swizzle: chunk' = chunk ^ (row&7). 2 CTAs/SM.
#define PLANE_BYTES 16384                 // 128 rows x 128B
#define BUF_BYTES (2*PLANE_BYTES)         // 32768
#define GEMM_SMEM (3*BUF_BYTES)           // 98304

#define SWZ_ADDR(base, row, chunk) \
    ((base) + (uint32_t)(row)*128u + (uint32_t)(((chunk) ^ ((row)&7)) << 4))

template<int EPI>
__global__ __launch_bounds__(256, 2)
void gemm_mma(const __half* __restrict__ Ah, const __half* __restrict__ Bh,
              const float* __restrict__ bias, const float* __restrict__ res,
              float* __restrict__ Cf, __half* __restrict__ Chi, int N, int K) {
    extern __shared__ char gsm[];
    uint32_t sb = smem_to_u32(gsm);
    int tid = threadIdx.x, lane = tid & 31, wid = tid >> 5;
    int rowBase = blockIdx.y * 128, colBase = blockIdx.x * 128;

    int wm = wid & 3, wn = wid >> 2;      // 4x2 warp grid
    int m0 = wm * 32, n0 = wn * 64;

    float acc[2][8][4];
    #pragma unroll
    for (int i = 0; i < 2; i++)
        #pragma unroll
        for (int j = 0; j < 8; j++)
            #pragma unroll
            for (int q = 0; q < 4; q++) acc[i][j][q] = 0.f;

    int arow_l = (lane & 15);
    int acb    = (lane >> 4);
    int brow_l = (lane & 7) + ((lane >> 4) << 3);
    int bcb    = (lane >> 3) & 1;

    auto load_chunk = [&](int buf, int k0) {
        uint32_t sbase = sb + buf * BUF_BYTES;
        int row = tid >> 1, c0 = (tid & 1) * 4;
        size_t goA = (size_t)(rowBase + row) * K + k0 + c0 * 8;
        size_t goB = (size_t)(colBase + row) * K + k0 + c0 * 8;
        #pragma unroll
        for (int j = 0; j < 4; j++) {
            uint32_t so = SWZ_ADDR(sbase, row, c0 + j);
            cp_async16(so,               Ah + goA + j * 8);
            cp_async16(PLANE_BYTES + so, Bh + goB + j * 8);
        }
    };

    int NC = K >> 6;
    load_chunk(0, 0);
    CP_COMMIT();
    load_chunk(1, 64);
    CP_COMMIT();

    int bufc = 0, bufn = 2;
    for (int c = 0; c < NC; c++) {
        // entry invariant: groups pending for chunks c, c+1 (or just c at the end)
        if (c + 1 < NC) { CP_WAIT1(); } else { CP_WAIT0(); }
        __syncthreads();   // also separates prior compute on bufn from the load below
        if (c + 2 < NC) {
            load_chunk(bufn, (c + 2) << 6);
            CP_COMMIT();
        }

        uint32_t pA = sb + bufc * BUF_BYTES;
        #pragma unroll
        for (int ks = 0; ks < 4; ks++) {
            uint32_t ah[2][4];
            #pragma unroll
            for (int mt = 0; mt < 2; mt++) {
                int ar = m0 + mt * 16 + arow_l;
                uint32_t ad = SWZ_ADDR(pA, ar, ks * 2 + acb);
                ldsm_x4(ah[mt][0], ah[mt][1], ah[mt][2], ah[mt][3], ad);
            }
            #pragma unroll
            for (int ng = 0; ng < 4; ng++) {
                int br = n0 + ng * 16 + brow_l;
                uint32_t bd = SWZ_ADDR(pA + PLANE_BYTES, br, ks * 2 + bcb);
                uint32_t bh2[2][2];
                ldsm_x4(bh2[0][0], bh2[0][1], bh2[1][0], bh2[1][1], bd);
                #pragma unroll
                for (int mt = 0; mt < 2; mt++)
                    #pragma unroll
                    for (int j = 0; j < 2; j++)
                        mma_f16(acc[mt][2*ng + j], ah[mt], bh2[j]);
            }
        }
        bufc = (bufc + 1 == 3) ? 0 : bufc + 1;
        bufn = (bufn + 1 == 3) ? 0 : bufn + 1;
    }

    // ---- epilogue ----
    int rbase = rowBase + m0 + (lane >> 2);
    int cbase = colBase + n0 + (lane & 3) * 2;
    #pragma unroll
    for (int mt = 0; mt < 2; mt++) {
        #pragma unroll
        for (int half = 0; half < 2; half++) {
            int row = rbase + mt * 16 + half * 8;
            if (EPI == 0) {
                float* crow = Cf + (size_t)row * N;
                const float* rrow = res + (size_t)row * N;
                #pragma unroll
                for (int nt = 0; nt < 8; nt++) {
                    int col = cbase + nt * 8;
                    float2 o;
                    o.x = acc[mt][nt][half*2+0] + bias[col]   + rrow[col];
                    o.y = acc[mt][nt][half*2+1] + bias[col+1] + rrow[col+1];
                    *(float2*)(crow + col) = o;
                }
            } else {
                __half* hrow = Chi + (size_t)row * N;
                #pragma unroll
                for (int nt = 0; nt < 8; nt++) {
                    int col = cbase + nt * 8;
                    float v0 = acc[mt][nt][half*2+0] + bias[col];
                    float v1 = acc[mt][nt][half*2+1] + bias[col+1];
                    v0 = 0.5f * v0 * (1.0f + erff(v0 * 0.70710678118654752f));
                    v1 = 0.5f * v1 * (1.0f + erff(v1 * 0.70710678118654752f));
                    __half hh[2] = {__float2half(v0), __float2half(v1)};
                    *(uint32_t*)(hrow + col) = *(uint32_t*)hh;
                }
            }
        }
    }
}

// ---------------- launch ----------------
extern "C" void kernel_launch(void* const* d_in, const int* in_sizes, int n_in,
                              void* d_out, int out_size) {
    const float* x      = (const float*)d_in[0];
    const float* wrf    = (const float*)d_in[1];
    const float* kqv_w  = (const float*)d_in[2];
    const float* kqv_b  = (const float*)d_in[3];
    const float* proj_w = (const float*)d_in[4];
    const float* proj_b = (const float*)d_in[5];
    const float* ln1_g  = (const float*)d_in[6];
    const float* ln1_b  = (const float*)d_in[7];
    const float* ln2_g  = (const float*)d_in[8];
    const float* ln2_b  = (const float*)d_in[9];
    const float* mlp_w1 = (const float*)d_in[10];
    const float* mlp_b1 = (const float*)d_in[11];
    const float* mlp_w2 = (const float*)d_in[12];
    const float* mlp_b2 = (const float*)d_in[13];
    float* out = (float*)d_out;

    float *p_v, *p_qp, *p_kp, *p_pk, *p_ps, *p_kptv, *p_ksum, *p_x1;
    __half *p_h2h, *p_yh, *p_hidh, *p_pwh, *p_w1h, *p_w2h;
    cudaGetSymbolAddress((void**)&p_v,    g_v);
    cudaGetSymbolAddress((void**)&p_qp,   g_qp);
    cudaGetSymbolAddress((void**)&p_kp,   g_kp);
    cudaGetSymbolAddress((void**)&p_pk,   g_kptv_part);
    cudaGetSymbolAddress((void**)&p_ps,   g_ksum_part);
    cudaGetSymbolAddress((void**)&p_kptv, g_kptv);
    cudaGetSymbolAddress((void**)&p_ksum, g_ksum);
    cudaGetSymbolAddress((void**)&p_x1,   g_x1);
    cudaGetSymbolAddress((void**)&p_h2h,  g_h2h);
    cudaGetSymbolAddress((void**)&p_yh,   g_yh);
    cudaGetSymbolAddress((void**)&p_hidh, g_hidh);
    cudaGetSymbolAddress((void**)&p_pwh,  g_pwh);
    cudaGetSymbolAddress((void**)&p_w1h,  g_w1h);
    cudaGetSymbolAddress((void**)&p_w2h,  g_w2h);

    const size_t k1_smem = (size_t)K1_SMEM_FLOATS * sizeof(float);
    cudaFuncSetAttribute(kqv_prm_kernel, cudaFuncAttributeMaxDynamicSharedMemorySize,
                         (int)k1_smem);
    cudaFuncSetAttribute(gemm_mma<0>, cudaFuncAttributeMaxDynamicSharedMemorySize, GEMM_SMEM);
    cudaFuncSetAttribute(gemm_mma<1>, cudaFuncAttributeMaxDynamicSharedMemorySize, GEMM_SMEM);

    // 0. all weight fp16 rounds (one launch)
    cvt_all_kernel<<<(CVT_N4 + 255)/256, 256>>>(proj_w, mlp_w1, mlp_w2, p_pwh, p_w1h, p_w2h);
    // 1. fused LN1 + kqv + prm_exp
    kqv_prm_kernel<<<NTOK/8, 256, k1_smem>>>(x, ln1_g, ln1_b, kqv_w, kqv_b, wrf,
                                             p_v, p_kp, p_qp);
    // 2-3. kptv/ksum reduction over T
    kpt_kernel<<<dim3(16, 64), 256>>>(p_v, p_kp, p_pk, p_ps);
    reduce_kernel<<<513, 256>>>(p_pk, p_ps, p_kptv, p_ksum);
    // 4. y (fp16)
    y_kernel<<<dim3(TQ/256, 64), 256>>>(p_qp, p_kptv, p_ksum, p_yh);
    // 5. attn proj + residual -> x1 (fp32)
    gemm_mma<0><<<dim3(EMB/128, NTOK/128), 256, GEMM_SMEM>>>(
        p_yh, p_pwh, proj_b, x, p_x1, nullptr, EMB, EMB);
    // 6. LN2 -> fp16
    ln2_kernel<<<NTOK/8, 256>>>(p_x1, ln2_g, ln2_b, p_h2h);
    // 7. mlp1 + gelu -> hid (fp16)
    gemm_mma<1><<<dim3(HID/128, NTOK/128), 256, GEMM_SMEM>>>(
        p_h2h, p_w1h, mlp_b1, nullptr, nullptr, p_hidh, HID, EMB);
    // 8. mlp2 + residual -> out (fp32)
    gemm_mma<0><<<dim3(EMB/128, NTOK/128), 256, GEMM_SMEM>>>(
        p_hidh, p_w2h, mlp_b2, p_x1, out, nullptr, EMB, HID);
}